// round 1
// baseline (speedup 1.0000x reference)
#include <cuda_runtime.h>
#include <math.h>

#define BB 2
#define NN 2048
#define CC 1024
#define HH 16
#define DD 64
#define MR (BB*NN)          // 4096 rows
#define QK_SCALE 0.125f     // 64^-0.5

// Scratch (allocation-free rule: device globals)
__device__ float g_qkv[(size_t)MR * 3 * CC];   // [4096][3072]  q|k|v
__device__ float g_attn[(size_t)MR * CC];      // [4096][1024]

// ---------------------------------------------------------------------------
// GEMM: Cm[M,Nc] = A[M,K] @ W[Nc,K]^T (+ bias). 128x128x8 tile, 8x8/thread.
// ---------------------------------------------------------------------------
__global__ __launch_bounds__(256) void gemm_nt(const float* __restrict__ A,
                                               const float* __restrict__ W,
                                               const float* __restrict__ bias,
                                               float* __restrict__ Cm,
                                               int M, int Nc, int K) {
    __shared__ float As[8][128];
    __shared__ float Bs[8][128];

    const int tid = threadIdx.x;
    const int m0 = blockIdx.y * 128;
    const int n0 = blockIdx.x * 128;

    const int lrow = tid >> 1;          // 0..127
    const int lcol = (tid & 1) * 4;     // 0 or 4

    const float* Ag = A + (size_t)(m0 + lrow) * K + lcol;
    const float* Wg = W + (size_t)(n0 + lrow) * K + lcol;

    const int trow = (tid >> 4) * 8;    // 0..120
    const int tcol = (tid & 15) * 8;    // 0..120

    float acc[8][8];
#pragma unroll
    for (int i = 0; i < 8; i++)
#pragma unroll
        for (int j = 0; j < 8; j++) acc[i][j] = 0.f;

    for (int k0 = 0; k0 < K; k0 += 8) {
        float4 av = *(const float4*)(Ag + k0);
        float4 wv = *(const float4*)(Wg + k0);
        As[lcol + 0][lrow] = av.x;
        As[lcol + 1][lrow] = av.y;
        As[lcol + 2][lrow] = av.z;
        As[lcol + 3][lrow] = av.w;
        Bs[lcol + 0][lrow] = wv.x;
        Bs[lcol + 1][lrow] = wv.y;
        Bs[lcol + 2][lrow] = wv.z;
        Bs[lcol + 3][lrow] = wv.w;
        __syncthreads();

#pragma unroll
        for (int kk = 0; kk < 8; kk++) {
            float ra[8], rb[8];
#pragma unroll
            for (int i = 0; i < 8; i++) ra[i] = As[kk][trow + i];
#pragma unroll
            for (int j = 0; j < 8; j++) rb[j] = Bs[kk][tcol + j];
#pragma unroll
            for (int i = 0; i < 8; i++)
#pragma unroll
                for (int j = 0; j < 8; j++) acc[i][j] += ra[i] * rb[j];
        }
        __syncthreads();
    }

#pragma unroll
    for (int i = 0; i < 8; i++) {
        float* cp = Cm + (size_t)(m0 + trow + i) * Nc + n0 + tcol;
#pragma unroll
        for (int j = 0; j < 8; j++) {
            float v = acc[i][j];
            if (bias) v += bias[n0 + tcol + j];
            cp[j] = v;
        }
    }
}

// ---------------------------------------------------------------------------
// RoPE in-place on q and k slices of g_qkv.
// idx layout: b(1) n(11) h(4) i(5)  -> total 2^21 threads
// ---------------------------------------------------------------------------
__global__ void rotary_kernel(float* __restrict__ qkv,
                              const float* __restrict__ freqs) {
    int idx = blockIdx.x * blockDim.x + threadIdx.x;
    int i = idx & 31;
    int h = (idx >> 5) & 15;
    int n = (idx >> 9) & (NN - 1);
    int b = idx >> 20;

    float f = freqs[n * (DD / 2) + i];
    float c = cosf(f), s = sinf(f);

    float* p = qkv + (size_t)(b * NN + n) * 3 * CC + h * DD + 2 * i;
    // q
    float x1 = p[0], x2 = p[1];
    p[0] = x1 * c - x2 * s;
    p[1] = x1 * s + x2 * c;
    // k
    p += CC;
    x1 = p[0]; x2 = p[1];
    p[0] = x1 * c - x2 * s;
    p[1] = x1 * s + x2 * c;
}

// ---------------------------------------------------------------------------
// Flash attention, fp32. Block = 64 q-rows x one head x one batch. 256 thr.
// Thread t: q-row r = t>>2, quad c4 = t&3 owns 16-wide segment seg = c4*16
// (k-columns of S, d-columns of O). q and P exchanged via width-4 shuffles.
// ---------------------------------------------------------------------------
__global__ __launch_bounds__(256) void attn_kernel(const float* __restrict__ qkv,
                                                   float* __restrict__ outp) {
    __shared__ float Kts[DD][68];    // K transposed: [d][k-row], padded stride
    __shared__ float Vs[64][DD];     // V: [k-row][d]

    const int t = threadIdx.x;
    const int r = t >> 2;
    const int seg = (t & 3) * 16;
    const int h = blockIdx.y;
    const int b = blockIdx.z;
    const int q0 = blockIdx.x * 64;
    const size_t rstride = 3 * CC;

    // load my q segment (d = seg..seg+15), pre-scaled
    const float* qp = qkv + (size_t)(b * NN + q0 + r) * rstride + h * DD + seg;
    float qreg[16];
#pragma unroll
    for (int j = 0; j < 16; j += 4) {
        float4 v = *(const float4*)(qp + j);
        qreg[j] = v.x * QK_SCALE; qreg[j + 1] = v.y * QK_SCALE;
        qreg[j + 2] = v.z * QK_SCALE; qreg[j + 3] = v.w * QK_SCALE;
    }

    float m = -1e30f, l = 0.f;
    float o[16];
#pragma unroll
    for (int j = 0; j < 16; j++) o[j] = 0.f;

    for (int kt = 0; kt < NN / 64; kt++) {
        __syncthreads();
        // stage K (transposed) and V tiles
        const float* kp = qkv + (size_t)(b * NN + kt * 64 + r) * rstride + CC + h * DD + seg;
        const float* vp = kp + CC;
        {
            float4 k0 = *(const float4*)(kp + 0);
            float4 k1 = *(const float4*)(kp + 4);
            float4 k2 = *(const float4*)(kp + 8);
            float4 k3 = *(const float4*)(kp + 12);
            Kts[seg + 0][r] = k0.x;  Kts[seg + 1][r] = k0.y;
            Kts[seg + 2][r] = k0.z;  Kts[seg + 3][r] = k0.w;
            Kts[seg + 4][r] = k1.x;  Kts[seg + 5][r] = k1.y;
            Kts[seg + 6][r] = k1.z;  Kts[seg + 7][r] = k1.w;
            Kts[seg + 8][r] = k2.x;  Kts[seg + 9][r] = k2.y;
            Kts[seg + 10][r] = k2.z; Kts[seg + 11][r] = k2.w;
            Kts[seg + 12][r] = k3.x; Kts[seg + 13][r] = k3.y;
            Kts[seg + 14][r] = k3.z; Kts[seg + 15][r] = k3.w;
#pragma unroll
            for (int j = 0; j < 16; j += 4)
                *(float4*)&Vs[r][seg + j] = *(const float4*)(vp + j);
        }
        __syncthreads();

        // S segment: s[j] = q(row r) . k(row seg+j)
        float s[16];
#pragma unroll
        for (int j = 0; j < 16; j++) s[j] = 0.f;
#pragma unroll
        for (int src = 0; src < 4; src++) {
#pragma unroll
            for (int jj = 0; jj < 16; jj++) {
                float qv = __shfl_sync(0xffffffffu, qreg[jj], src, 4);
                const float4* kr = (const float4*)&Kts[src * 16 + jj][seg];
                float4 k0 = kr[0], k1 = kr[1], k2 = kr[2], k3 = kr[3];
                s[0] += qv * k0.x;  s[1] += qv * k0.y;
                s[2] += qv * k0.z;  s[3] += qv * k0.w;
                s[4] += qv * k1.x;  s[5] += qv * k1.y;
                s[6] += qv * k1.z;  s[7] += qv * k1.w;
                s[8] += qv * k2.x;  s[9] += qv * k2.y;
                s[10] += qv * k2.z; s[11] += qv * k2.w;
                s[12] += qv * k3.x; s[13] += qv * k3.y;
                s[14] += qv * k3.z; s[15] += qv * k3.w;
            }
        }

        // online softmax (reduce across the 4-lane quad)
        float tmax = s[0];
#pragma unroll
        for (int j = 1; j < 16; j++) tmax = fmaxf(tmax, s[j]);
        tmax = fmaxf(tmax, __shfl_xor_sync(0xffffffffu, tmax, 1, 4));
        tmax = fmaxf(tmax, __shfl_xor_sync(0xffffffffu, tmax, 2, 4));
        float mnew = fmaxf(m, tmax);
        float alpha = __expf(m - mnew);
        float rsum = 0.f;
#pragma unroll
        for (int j = 0; j < 16; j++) {
            s[j] = __expf(s[j] - mnew);   // s becomes p
            rsum += s[j];
        }
        rsum += __shfl_xor_sync(0xffffffffu, rsum, 1, 4);
        rsum += __shfl_xor_sync(0xffffffffu, rsum, 2, 4);
        l = l * alpha + rsum;
        m = mnew;
#pragma unroll
        for (int j = 0; j < 16; j++) o[j] *= alpha;

        // O += P @ V  (o segment: d = seg..seg+15)
#pragma unroll
        for (int src = 0; src < 4; src++) {
#pragma unroll
            for (int jj = 0; jj < 16; jj++) {
                float pv = __shfl_sync(0xffffffffu, s[jj], src, 4);
                const float4* vr = (const float4*)&Vs[src * 16 + jj][seg];
                float4 v0 = vr[0], v1 = vr[1], v2 = vr[2], v3 = vr[3];
                o[0] += pv * v0.x;  o[1] += pv * v0.y;
                o[2] += pv * v0.z;  o[3] += pv * v0.w;
                o[4] += pv * v1.x;  o[5] += pv * v1.y;
                o[6] += pv * v1.z;  o[7] += pv * v1.w;
                o[8] += pv * v2.x;  o[9] += pv * v2.y;
                o[10] += pv * v2.z; o[11] += pv * v2.w;
                o[12] += pv * v3.x; o[13] += pv * v3.y;
                o[14] += pv * v3.z; o[15] += pv * v3.w;
            }
        }
    }

    float inv = 1.f / l;
    float* op = outp + (size_t)(b * NN + q0 + r) * CC + h * DD + seg;
#pragma unroll
    for (int j = 0; j < 16; j += 4) {
        float4 v;
        v.x = o[j] * inv; v.y = o[j + 1] * inv;
        v.z = o[j + 2] * inv; v.w = o[j + 3] * inv;
        *(float4*)(op + j) = v;
    }
}

// ---------------------------------------------------------------------------
extern "C" void kernel_launch(void* const* d_in, const int* in_sizes, int n_in,
                              void* d_out, int out_size) {
    const float* x      = (const float*)d_in[0];
    const float* freqs  = (const float*)d_in[1];
    const float* w_qkv  = (const float*)d_in[2];
    const float* w_proj = (const float*)d_in[3];
    const float* b_proj = (const float*)d_in[4];
    float* out = (float*)d_out;

    float *qkv, *attn;
    cudaGetSymbolAddress((void**)&qkv, g_qkv);
    cudaGetSymbolAddress((void**)&attn, g_attn);

    // 1) qkv = x @ w_qkv^T
    gemm_nt<<<dim3(3 * CC / 128, MR / 128), 256>>>(x, w_qkv, nullptr, qkv,
                                                   MR, 3 * CC, CC);
    // 2) RoPE on q,k
    rotary_kernel<<<(BB * NN * HH * (DD / 2)) / 256, 256>>>(qkv, freqs);
    // 3) attention
    attn_kernel<<<dim3(NN / 64, HH, BB), 256>>>(qkv, attn);
    // 4) out = attn @ w_proj^T + b_proj
    gemm_nt<<<dim3(CC / 128, MR / 128), 256>>>(attn, w_proj, b_proj, out,
                                               MR, CC, CC);
}

// round 2
// speedup vs baseline: 2.2865x; 2.2865x over previous
#include <cuda_runtime.h>
#include <math.h>

#define BB 2
#define NN 2048
#define CC 1024
#define HH 16
#define DD 64
#define MR (BB*NN)          // 4096 rows
#define QK_SCALE 0.125f     // 64^-0.5

// Scratch (allocation-free rule: device globals)
__device__ float g_qkv[(size_t)MR * 3 * CC];   // [4096][3072]  q|k|v
__device__ float g_attn[(size_t)MR * CC];      // [4096][1024]

typedef unsigned long long u64;

// ---- packed fp32x2 helpers (Blackwell FFMA2 path) -------------------------
__device__ __forceinline__ u64 splat2(float x) {
    u64 r;
    asm("mov.b64 %0, {%1, %1};" : "=l"(r) : "f"(x));
    return r;
}
__device__ __forceinline__ void ffma2(float2& d, u64 a, u64 b) {
    asm("fma.rn.f32x2 %0, %1, %2, %0;"
        : "+l"(reinterpret_cast<u64&>(d)) : "l"(a), "l"(b));
}

// ---------------------------------------------------------------------------
// GEMM: Cm[M,Nc] = A[M,K] @ W[Nc,K]^T (+ bias). 128x128x16 tile, 8x8/thread,
// inner product via fp32x2 packed FMAs.
// ---------------------------------------------------------------------------
__global__ __launch_bounds__(256) void gemm_nt(const float* __restrict__ A,
                                               const float* __restrict__ W,
                                               const float* __restrict__ bias,
                                               float* __restrict__ Cm,
                                               int M, int Nc, int K) {
    __shared__ float As[16][128];
    __shared__ float Bs[16][128];

    const int tid = threadIdx.x;
    const int m0 = blockIdx.y * 128;
    const int n0 = blockIdx.x * 128;

    const int lrow = tid >> 1;          // 0..127
    const int lcol = (tid & 1) * 8;     // 0 or 8

    const float* Ag = A + (size_t)(m0 + lrow) * K + lcol;
    const float* Wg = W + (size_t)(n0 + lrow) * K + lcol;

    const int trow = (tid >> 4) * 8;    // 0..120
    const int tcol = (tid & 15) * 8;    // 0..120

    float2 acc[8][4];
#pragma unroll
    for (int i = 0; i < 8; i++)
#pragma unroll
        for (int j = 0; j < 4; j++) acc[i][j] = make_float2(0.f, 0.f);

    for (int k0 = 0; k0 < K; k0 += 16) {
        float4 av0 = *(const float4*)(Ag + k0);
        float4 av1 = *(const float4*)(Ag + k0 + 4);
        float4 wv0 = *(const float4*)(Wg + k0);
        float4 wv1 = *(const float4*)(Wg + k0 + 4);
        As[lcol + 0][lrow] = av0.x;  As[lcol + 1][lrow] = av0.y;
        As[lcol + 2][lrow] = av0.z;  As[lcol + 3][lrow] = av0.w;
        As[lcol + 4][lrow] = av1.x;  As[lcol + 5][lrow] = av1.y;
        As[lcol + 6][lrow] = av1.z;  As[lcol + 7][lrow] = av1.w;
        Bs[lcol + 0][lrow] = wv0.x;  Bs[lcol + 1][lrow] = wv0.y;
        Bs[lcol + 2][lrow] = wv0.z;  Bs[lcol + 3][lrow] = wv0.w;
        Bs[lcol + 4][lrow] = wv1.x;  Bs[lcol + 5][lrow] = wv1.y;
        Bs[lcol + 6][lrow] = wv1.z;  Bs[lcol + 7][lrow] = wv1.w;
        __syncthreads();

#pragma unroll
        for (int kk = 0; kk < 16; kk++) {
            float4 a0 = *(const float4*)&As[kk][trow];
            float4 a1 = *(const float4*)&As[kk][trow + 4];
            ulonglong2 bp0 = *(const ulonglong2*)&Bs[kk][tcol];
            ulonglong2 bp1 = *(const ulonglong2*)&Bs[kk][tcol + 4];
            u64 b0 = bp0.x, b1 = bp0.y, b2 = bp1.x, b3 = bp1.y;
            float av[8] = {a0.x, a0.y, a0.z, a0.w, a1.x, a1.y, a1.z, a1.w};
#pragma unroll
            for (int i = 0; i < 8; i++) {
                u64 sa = splat2(av[i]);
                ffma2(acc[i][0], sa, b0);
                ffma2(acc[i][1], sa, b1);
                ffma2(acc[i][2], sa, b2);
                ffma2(acc[i][3], sa, b3);
            }
        }
        __syncthreads();
    }

#pragma unroll
    for (int i = 0; i < 8; i++) {
        float* cp = Cm + (size_t)(m0 + trow + i) * Nc + n0 + tcol;
#pragma unroll
        for (int j = 0; j < 4; j++) {
            float vx = acc[i][j].x;
            float vy = acc[i][j].y;
            if (bias) {
                vx += bias[n0 + tcol + 2 * j];
                vy += bias[n0 + tcol + 2 * j + 1];
            }
            cp[2 * j] = vx;
            cp[2 * j + 1] = vy;
        }
    }
}

// ---------------------------------------------------------------------------
// RoPE in-place on q and k slices of g_qkv.
// ---------------------------------------------------------------------------
__global__ void rotary_kernel(float* __restrict__ qkv,
                              const float* __restrict__ freqs) {
    int idx = blockIdx.x * blockDim.x + threadIdx.x;
    int i = idx & 31;
    int h = (idx >> 5) & 15;
    int n = (idx >> 9) & (NN - 1);
    int b = idx >> 20;

    float f = freqs[n * (DD / 2) + i];
    float c = cosf(f), s = sinf(f);

    float* p = qkv + (size_t)(b * NN + n) * 3 * CC + h * DD + 2 * i;
    float x1 = p[0], x2 = p[1];
    p[0] = x1 * c - x2 * s;
    p[1] = x1 * s + x2 * c;
    p += CC;
    x1 = p[0]; x2 = p[1];
    p[0] = x1 * c - x2 * s;
    p[1] = x1 * s + x2 * c;
}

// ---------------------------------------------------------------------------
// Flash attention, fp32x2, register-tiled.
// Block = 64 q-rows x one head x one batch, 256 threads as 16x16.
// Thread (ty,tx): q rows ty*4..+3, k/d cols tx*4..+3. S and O GEMMs are
// outer-product register-tiled; P redistributed for O GEMM via lane shuffles.
// ---------------------------------------------------------------------------
__global__ __launch_bounds__(256) void attn_kernel(const float* __restrict__ qkv,
                                                   float* __restrict__ outp) {
    __shared__ float Qs[DD][64];   // transposed: [d][q]
    __shared__ float Ks[DD][64];   // transposed: [d][k]
    __shared__ float Vs[64][DD];   // [k][d]

    const int t = threadIdx.x;
    const int ty = t >> 4;          // q group 0..15
    const int tx = t & 15;          // k/d group 0..15
    const int lane = t & 31;
    const int srcbase = lane & 16;  // same-ty half of the warp
    const int h = blockIdx.y;
    const int b = blockIdx.z;
    const int q0 = blockIdx.x * 64;
    const size_t rstride = 3 * CC;

    // stage Q tile transposed + pre-scaled
    {
        int qr = t >> 2, dseg = (t & 3) * 16;
        const float* qp = qkv + (size_t)(b * NN + q0 + qr) * rstride + h * DD + dseg;
#pragma unroll
        for (int j = 0; j < 16; j += 4) {
            float4 v = *(const float4*)(qp + j);
            Qs[dseg + j + 0][qr] = v.x * QK_SCALE;
            Qs[dseg + j + 1][qr] = v.y * QK_SCALE;
            Qs[dseg + j + 2][qr] = v.z * QK_SCALE;
            Qs[dseg + j + 3][qr] = v.w * QK_SCALE;
        }
    }

    float2 o[4][2];
    float mr[4], lr[4];
#pragma unroll
    for (int i = 0; i < 4; i++) {
        o[i][0] = make_float2(0.f, 0.f);
        o[i][1] = make_float2(0.f, 0.f);
        mr[i] = -1e30f;
        lr[i] = 0.f;
    }

    for (int kt = 0; kt < NN / 64; kt++) {
        __syncthreads();
        {   // stage K (transposed) and V
            int kr = t >> 2, dseg = (t & 3) * 16;
            const float* kp = qkv + (size_t)(b * NN + kt * 64 + kr) * rstride
                              + CC + h * DD + dseg;
            const float* vp = kp + CC;
#pragma unroll
            for (int j = 0; j < 16; j += 4) {
                float4 kv = *(const float4*)(kp + j);
                Ks[dseg + j + 0][kr] = kv.x;
                Ks[dseg + j + 1][kr] = kv.y;
                Ks[dseg + j + 2][kr] = kv.z;
                Ks[dseg + j + 3][kr] = kv.w;
                *(float4*)&Vs[kr][dseg + j] = *(const float4*)(vp + j);
            }
        }
        __syncthreads();

        // ---- S = Q K^T (64x64x64, 4x4 per thread, fp32x2) ----
        float2 s[4][2];
#pragma unroll
        for (int i = 0; i < 4; i++) {
            s[i][0] = make_float2(0.f, 0.f);
            s[i][1] = make_float2(0.f, 0.f);
        }
#pragma unroll 8
        for (int d = 0; d < DD; d++) {
            float4 aq = *(const float4*)&Qs[d][ty * 4];
            ulonglong2 bk = *(const ulonglong2*)&Ks[d][tx * 4];
            u64 b0 = bk.x, b1 = bk.y;
            u64 p0 = splat2(aq.x), p1 = splat2(aq.y);
            u64 p2 = splat2(aq.z), p3 = splat2(aq.w);
            ffma2(s[0][0], p0, b0); ffma2(s[0][1], p0, b1);
            ffma2(s[1][0], p1, b0); ffma2(s[1][1], p1, b1);
            ffma2(s[2][0], p2, b0); ffma2(s[2][1], p2, b1);
            ffma2(s[3][0], p3, b0); ffma2(s[3][1], p3, b1);
        }

        // ---- online softmax (row reduce across the 16 tx lanes) ----
#pragma unroll
        for (int qq = 0; qq < 4; qq++) {
            float2 a = s[qq][0], c = s[qq][1];
            float tm = fmaxf(fmaxf(a.x, a.y), fmaxf(c.x, c.y));
            tm = fmaxf(tm, __shfl_xor_sync(0xffffffffu, tm, 1));
            tm = fmaxf(tm, __shfl_xor_sync(0xffffffffu, tm, 2));
            tm = fmaxf(tm, __shfl_xor_sync(0xffffffffu, tm, 4));
            tm = fmaxf(tm, __shfl_xor_sync(0xffffffffu, tm, 8));
            float mn = fmaxf(mr[qq], tm);
            float al = __expf(mr[qq] - mn);
            mr[qq] = mn;
            a.x = __expf(a.x - mn); a.y = __expf(a.y - mn);
            c.x = __expf(c.x - mn); c.y = __expf(c.y - mn);
            s[qq][0] = a; s[qq][1] = c;
            float rs = a.x + a.y + c.x + c.y;
            rs += __shfl_xor_sync(0xffffffffu, rs, 1);
            rs += __shfl_xor_sync(0xffffffffu, rs, 2);
            rs += __shfl_xor_sync(0xffffffffu, rs, 4);
            rs += __shfl_xor_sync(0xffffffffu, rs, 8);
            lr[qq] = lr[qq] * al + rs;
            o[qq][0].x *= al; o[qq][0].y *= al;
            o[qq][1].x *= al; o[qq][1].y *= al;
        }

        // ---- O += P V (64x64x64; P fetched from owning lane via shuffle) ----
#pragma unroll 4
        for (int g = 0; g < 16; g++) {
            int src = srcbase | g;
#pragma unroll
            for (int kk = 0; kk < 4; kk++) {
                int k = g * 4 + kk;
                float pv0 = __shfl_sync(0xffffffffu,
                                        (kk & 1) ? s[0][kk >> 1].y : s[0][kk >> 1].x, src);
                float pv1 = __shfl_sync(0xffffffffu,
                                        (kk & 1) ? s[1][kk >> 1].y : s[1][kk >> 1].x, src);
                float pv2 = __shfl_sync(0xffffffffu,
                                        (kk & 1) ? s[2][kk >> 1].y : s[2][kk >> 1].x, src);
                float pv3 = __shfl_sync(0xffffffffu,
                                        (kk & 1) ? s[3][kk >> 1].y : s[3][kk >> 1].x, src);
                ulonglong2 vv = *(const ulonglong2*)&Vs[k][tx * 4];
                u64 v0 = vv.x, v1 = vv.y;
                u64 w0 = splat2(pv0), w1 = splat2(pv1);
                u64 w2 = splat2(pv2), w3 = splat2(pv3);
                ffma2(o[0][0], w0, v0); ffma2(o[0][1], w0, v1);
                ffma2(o[1][0], w1, v0); ffma2(o[1][1], w1, v1);
                ffma2(o[2][0], w2, v0); ffma2(o[2][1], w2, v1);
                ffma2(o[3][0], w3, v0); ffma2(o[3][1], w3, v1);
            }
        }
    }

    // ---- epilogue ----
#pragma unroll
    for (int qq = 0; qq < 4; qq++) {
        float inv = 1.f / lr[qq];
        float4 w;
        w.x = o[qq][0].x * inv; w.y = o[qq][0].y * inv;
        w.z = o[qq][1].x * inv; w.w = o[qq][1].y * inv;
        float* op = outp + (size_t)(b * NN + q0 + ty * 4 + qq) * CC + h * DD + tx * 4;
        *(float4*)op = w;
    }
}

// ---------------------------------------------------------------------------
extern "C" void kernel_launch(void* const* d_in, const int* in_sizes, int n_in,
                              void* d_out, int out_size) {
    const float* x      = (const float*)d_in[0];
    const float* freqs  = (const float*)d_in[1];
    const float* w_qkv  = (const float*)d_in[2];
    const float* w_proj = (const float*)d_in[3];
    const float* b_proj = (const float*)d_in[4];
    float* out = (float*)d_out;

    float *qkv, *attn;
    cudaGetSymbolAddress((void**)&qkv, g_qkv);
    cudaGetSymbolAddress((void**)&attn, g_attn);

    // 1) qkv = x @ w_qkv^T
    gemm_nt<<<dim3(3 * CC / 128, MR / 128), 256>>>(x, w_qkv, nullptr, qkv,
                                                   MR, 3 * CC, CC);
    // 2) RoPE on q,k
    rotary_kernel<<<(BB * NN * HH * (DD / 2)) / 256, 256>>>(qkv, freqs);
    // 3) attention
    attn_kernel<<<dim3(NN / 64, HH, BB), 256>>>(qkv, attn);
    // 4) out = attn @ w_proj^T + b_proj
    gemm_nt<<<dim3(CC / 128, MR / 128), 256>>>(attn, w_proj, b_proj, out,
                                               MR, CC, CC);
}

// round 4
// speedup vs baseline: 3.2636x; 1.4274x over previous
#include <cuda_runtime.h>
#include <cuda_bf16.h>
#include <math.h>
#include <stdint.h>

#define BB 2
#define NN 2048
#define CC 1024
#define HH 16
#define DD 64
#define MR (BB*NN)          // 4096 rows
#define QK_SCALE 0.125f     // 64^-0.5

// Scratch (allocation-free rule: device globals)
__device__ float g_qkv[(size_t)MR * 3 * CC];   // [4096][3072]  q|k|v
__device__ float g_attn[(size_t)MR * CC];      // [4096][1024]

typedef unsigned long long u64;

// ---- packed fp32x2 helpers (attention) ------------------------------------
__device__ __forceinline__ u64 splat2(float x) {
    u64 r;
    asm("mov.b64 %0, {%1, %1};" : "=l"(r) : "f"(x));
    return r;
}
__device__ __forceinline__ void ffma2(float2& d, u64 a, u64 b) {
    asm("fma.rn.f32x2 %0, %1, %2, %0;"
        : "+l"(reinterpret_cast<u64&>(d)) : "l"(a), "l"(b));
}

// ---- mma.sync helpers -----------------------------------------------------
__device__ __forceinline__ uint32_t smem_u32(const void* p) {
    return (uint32_t)__cvta_generic_to_shared(p);
}
__device__ __forceinline__ void ldmx4(uint32_t* r, uint32_t addr) {
    asm volatile("ldmatrix.sync.aligned.m8n8.x4.shared.b16 {%0,%1,%2,%3}, [%4];"
                 : "=r"(r[0]), "=r"(r[1]), "=r"(r[2]), "=r"(r[3]) : "r"(addr));
}
__device__ __forceinline__ void mma_bf16(float* c, const uint32_t* a, const uint32_t* b) {
    asm volatile(
        "mma.sync.aligned.m16n8k16.row.col.f32.bf16.bf16.f32 "
        "{%0,%1,%2,%3}, {%4,%5,%6,%7}, {%8,%9}, {%0,%1,%2,%3};"
        : "+f"(c[0]), "+f"(c[1]), "+f"(c[2]), "+f"(c[3])
        : "r"(a[0]), "r"(a[1]), "r"(a[2]), "r"(a[3]), "r"(b[0]), "r"(b[1]));
}
__device__ __forceinline__ uint32_t pack2bf(float x, float y) {
    __nv_bfloat162 h = __floats2bfloat162_rn(x, y);
    return *(uint32_t*)&h;
}

// ---------------------------------------------------------------------------
// Tensor-core GEMM via mma.sync bf16 + hi/lo split.
// Cm[M,Nc] = A[M,K] @ W[Nc,K]^T (+bias), fp32 I/O.
// CTA 128x128, K-chunk 32. 8 warps, warp tile 64x32 (4 m16 x 4 n8).
// ---------------------------------------------------------------------------
#define SPAD 40   // bf16 elements per smem row (32 data + 8 pad)

__global__ __launch_bounds__(256) void gemm_mma(const float* __restrict__ A,
                                                const float* __restrict__ W,
                                                const float* __restrict__ bias,
                                                float* __restrict__ Cm,
                                                int M, int Nc, int K) {
    __shared__ __nv_bfloat16 Ah[128][SPAD];
    __shared__ __nv_bfloat16 Al[128][SPAD];
    __shared__ __nv_bfloat16 Bh[128][SPAD];
    __shared__ __nv_bfloat16 Bl[128][SPAD];

    const int tid = threadIdx.x;
    const int wid = tid >> 5;
    const int lane = tid & 31;
    const int m0 = blockIdx.y * 128;
    const int n0 = blockIdx.x * 128;

    const int wm = (wid >> 2) * 64;   // warp m offset in tile
    const int wn = (wid & 3) * 32;    // warp n offset in tile

    // loader mapping: row 0..127, 16 consecutive floats
    const int lrow = tid >> 1;
    const int lcol = (tid & 1) * 16;
    const float* Ag = A + (size_t)(m0 + lrow) * K + lcol;
    const float* Wg = W + (size_t)(n0 + lrow) * K + lcol;

    float acc[4][4][4];   // [mt][nt][frag]
#pragma unroll
    for (int i = 0; i < 4; i++)
#pragma unroll
        for (int j = 0; j < 4; j++)
#pragma unroll
            for (int f = 0; f < 4; f++) acc[i][j][f] = 0.f;

    // ldmatrix source addresses (per k-step, add k16*2 bytes offset)
    // A: row = wm + (lane&15), col = (lane>>4)*8
    const uint32_t a_row = wm + (lane & 15);
    const uint32_t a_coff = (lane >> 4) * 8;
    // B: row = wn + ((lane>>4)<<3) + (lane&7), col = ((lane>>3)&1)*8
    const uint32_t b_row = wn + ((lane >> 4) << 3) + (lane & 7);
    const uint32_t b_coff = ((lane >> 3) & 1) * 8;

    const uint32_t sAh = smem_u32(Ah), sAl = smem_u32(Al);
    const uint32_t sBh = smem_u32(Bh), sBl = smem_u32(Bl);

    for (int k0 = 0; k0 < K; k0 += 32) {
        // ---- stage + split 128x32 fp32 -> hi/lo bf16 ----
#pragma unroll
        for (int j = 0; j < 16; j += 4) {
            float4 va = *(const float4*)(Ag + k0 + j);
            float4 vb = *(const float4*)(Wg + k0 + j);
            int c = lcol + j;

            float h0 = __bfloat162float(__float2bfloat16(va.x));
            float h1 = __bfloat162float(__float2bfloat16(va.y));
            float h2 = __bfloat162float(__float2bfloat16(va.z));
            float h3 = __bfloat162float(__float2bfloat16(va.w));
            *(uint32_t*)&Ah[lrow][c]     = pack2bf(h0, h1);
            *(uint32_t*)&Ah[lrow][c + 2] = pack2bf(h2, h3);
            *(uint32_t*)&Al[lrow][c]     = pack2bf(va.x - h0, va.y - h1);
            *(uint32_t*)&Al[lrow][c + 2] = pack2bf(va.z - h2, va.w - h3);

            h0 = __bfloat162float(__float2bfloat16(vb.x));
            h1 = __bfloat162float(__float2bfloat16(vb.y));
            h2 = __bfloat162float(__float2bfloat16(vb.z));
            h3 = __bfloat162float(__float2bfloat16(vb.w));
            *(uint32_t*)&Bh[lrow][c]     = pack2bf(h0, h1);
            *(uint32_t*)&Bh[lrow][c + 2] = pack2bf(h2, h3);
            *(uint32_t*)&Bl[lrow][c]     = pack2bf(vb.x - h0, vb.y - h1);
            *(uint32_t*)&Bl[lrow][c + 2] = pack2bf(vb.z - h2, vb.w - h3);
        }
        __syncthreads();

#pragma unroll
        for (int ks = 0; ks < 2; ks++) {
            const uint32_t kc = ks * 16;
            uint32_t afh[4][4], afl[4][4];
#pragma unroll
            for (int mt = 0; mt < 4; mt++) {
                uint32_t off = ((a_row + mt * 16) * SPAD + kc + a_coff) * 2;
                ldmx4(afh[mt], sAh + off);
                ldmx4(afl[mt], sAl + off);
            }
            uint32_t bfh[2][4], bfl[2][4];
#pragma unroll
            for (int bt = 0; bt < 2; bt++) {
                uint32_t off = ((b_row + bt * 16) * SPAD + kc + b_coff) * 2;
                ldmx4(bfh[bt], sBh + off);
                ldmx4(bfl[bt], sBl + off);
            }
#pragma unroll
            for (int mt = 0; mt < 4; mt++)
#pragma unroll
                for (int nt = 0; nt < 4; nt++) {
                    uint32_t* bh = &bfh[nt >> 1][(nt & 1) * 2];
                    uint32_t* bl = &bfl[nt >> 1][(nt & 1) * 2];
                    mma_bf16(acc[mt][nt], afh[mt], bh);   // hi*hi
                    mma_bf16(acc[mt][nt], afh[mt], bl);   // hi*lo
                    mma_bf16(acc[mt][nt], afl[mt], bh);   // lo*hi
                }
        }
        __syncthreads();
    }

    // ---- epilogue ----
    const int erow = lane >> 2;
    const int ecol = (lane & 3) * 2;
#pragma unroll
    for (int mt = 0; mt < 4; mt++) {
#pragma unroll
        for (int nt = 0; nt < 4; nt++) {
            int gr = m0 + wm + mt * 16 + erow;
            int gc = n0 + wn + nt * 8 + ecol;
            float b0 = 0.f, b1 = 0.f;
            if (bias) { b0 = bias[gc]; b1 = bias[gc + 1]; }
            float2 v0 = make_float2(acc[mt][nt][0] + b0, acc[mt][nt][1] + b1);
            float2 v1 = make_float2(acc[mt][nt][2] + b0, acc[mt][nt][3] + b1);
            *(float2*)(Cm + (size_t)gr * Nc + gc) = v0;
            *(float2*)(Cm + (size_t)(gr + 8) * Nc + gc) = v1;
        }
    }
}

// ---------------------------------------------------------------------------
// RoPE in-place on q and k slices of g_qkv.
// ---------------------------------------------------------------------------
__global__ void rotary_kernel(float* __restrict__ qkv,
                              const float* __restrict__ freqs) {
    int idx = blockIdx.x * blockDim.x + threadIdx.x;
    int i = idx & 31;
    int h = (idx >> 5) & 15;
    int n = (idx >> 9) & (NN - 1);
    int b = idx >> 20;

    float f = freqs[n * (DD / 2) + i];
    float c = cosf(f), s = sinf(f);

    float* p = qkv + (size_t)(b * NN + n) * 3 * CC + h * DD + 2 * i;
    float x1 = p[0], x2 = p[1];
    p[0] = x1 * c - x2 * s;
    p[1] = x1 * s + x2 * c;
    p += CC;
    x1 = p[0]; x2 = p[1];
    p[0] = x1 * c - x2 * s;
    p[1] = x1 * s + x2 * c;
}

// ---------------------------------------------------------------------------
// Flash attention, fp32x2, register-tiled (round-2 version, passing).
// ---------------------------------------------------------------------------
__global__ __launch_bounds__(256) void attn_kernel(const float* __restrict__ qkv,
                                                   float* __restrict__ outp) {
    __shared__ float Qs[DD][64];
    __shared__ float Ks[DD][64];
    __shared__ float Vs[64][DD];

    const int t = threadIdx.x;
    const int ty = t >> 4;
    const int tx = t & 15;
    const int lane = t & 31;
    const int srcbase = lane & 16;
    const int h = blockIdx.y;
    const int b = blockIdx.z;
    const int q0 = blockIdx.x * 64;
    const size_t rstride = 3 * CC;

    {
        int qr = t >> 2, dseg = (t & 3) * 16;
        const float* qp = qkv + (size_t)(b * NN + q0 + qr) * rstride + h * DD + dseg;
#pragma unroll
        for (int j = 0; j < 16; j += 4) {
            float4 v = *(const float4*)(qp + j);
            Qs[dseg + j + 0][qr] = v.x * QK_SCALE;
            Qs[dseg + j + 1][qr] = v.y * QK_SCALE;
            Qs[dseg + j + 2][qr] = v.z * QK_SCALE;
            Qs[dseg + j + 3][qr] = v.w * QK_SCALE;
        }
    }

    float2 o[4][2];
    float mr[4], lr[4];
#pragma unroll
    for (int i = 0; i < 4; i++) {
        o[i][0] = make_float2(0.f, 0.f);
        o[i][1] = make_float2(0.f, 0.f);
        mr[i] = -1e30f;
        lr[i] = 0.f;
    }

    for (int kt = 0; kt < NN / 64; kt++) {
        __syncthreads();
        {
            int kr = t >> 2, dseg = (t & 3) * 16;
            const float* kp = qkv + (size_t)(b * NN + kt * 64 + kr) * rstride
                              + CC + h * DD + dseg;
            const float* vp = kp + CC;
#pragma unroll
            for (int j = 0; j < 16; j += 4) {
                float4 kv = *(const float4*)(kp + j);
                Ks[dseg + j + 0][kr] = kv.x;
                Ks[dseg + j + 1][kr] = kv.y;
                Ks[dseg + j + 2][kr] = kv.z;
                Ks[dseg + j + 3][kr] = kv.w;
                *(float4*)&Vs[kr][dseg + j] = *(const float4*)(vp + j);
            }
        }
        __syncthreads();

        float2 s[4][2];
#pragma unroll
        for (int i = 0; i < 4; i++) {
            s[i][0] = make_float2(0.f, 0.f);
            s[i][1] = make_float2(0.f, 0.f);
        }
#pragma unroll 8
        for (int d = 0; d < DD; d++) {
            float4 aq = *(const float4*)&Qs[d][ty * 4];
            ulonglong2 bk = *(const ulonglong2*)&Ks[d][tx * 4];
            u64 b0 = bk.x, b1 = bk.y;
            u64 p0 = splat2(aq.x), p1 = splat2(aq.y);
            u64 p2 = splat2(aq.z), p3 = splat2(aq.w);
            ffma2(s[0][0], p0, b0); ffma2(s[0][1], p0, b1);
            ffma2(s[1][0], p1, b0); ffma2(s[1][1], p1, b1);
            ffma2(s[2][0], p2, b0); ffma2(s[2][1], p2, b1);
            ffma2(s[3][0], p3, b0); ffma2(s[3][1], p3, b1);
        }

#pragma unroll
        for (int qq = 0; qq < 4; qq++) {
            float2 a = s[qq][0], c = s[qq][1];
            float tm = fmaxf(fmaxf(a.x, a.y), fmaxf(c.x, c.y));
            tm = fmaxf(tm, __shfl_xor_sync(0xffffffffu, tm, 1));
            tm = fmaxf(tm, __shfl_xor_sync(0xffffffffu, tm, 2));
            tm = fmaxf(tm, __shfl_xor_sync(0xffffffffu, tm, 4));
            tm = fmaxf(tm, __shfl_xor_sync(0xffffffffu, tm, 8));
            float mn = fmaxf(mr[qq], tm);
            float al = __expf(mr[qq] - mn);
            mr[qq] = mn;
            a.x = __expf(a.x - mn); a.y = __expf(a.y - mn);
            c.x = __expf(c.x - mn); c.y = __expf(c.y - mn);
            s[qq][0] = a; s[qq][1] = c;
            float rs = a.x + a.y + c.x + c.y;
            rs += __shfl_xor_sync(0xffffffffu, rs, 1);
            rs += __shfl_xor_sync(0xffffffffu, rs, 2);
            rs += __shfl_xor_sync(0xffffffffu, rs, 4);
            rs += __shfl_xor_sync(0xffffffffu, rs, 8);
            lr[qq] = lr[qq] * al + rs;
            o[qq][0].x *= al; o[qq][0].y *= al;
            o[qq][1].x *= al; o[qq][1].y *= al;
        }

#pragma unroll 4
        for (int g = 0; g < 16; g++) {
            int src = srcbase | g;
#pragma unroll
            for (int kk = 0; kk < 4; kk++) {
                int k = g * 4 + kk;
                float pv0 = __shfl_sync(0xffffffffu,
                                        (kk & 1) ? s[0][kk >> 1].y : s[0][kk >> 1].x, src);
                float pv1 = __shfl_sync(0xffffffffu,
                                        (kk & 1) ? s[1][kk >> 1].y : s[1][kk >> 1].x, src);
                float pv2 = __shfl_sync(0xffffffffu,
                                        (kk & 1) ? s[2][kk >> 1].y : s[2][kk >> 1].x, src);
                float pv3 = __shfl_sync(0xffffffffu,
                                        (kk & 1) ? s[3][kk >> 1].y : s[3][kk >> 1].x, src);
                ulonglong2 vv = *(const ulonglong2*)&Vs[k][tx * 4];
                u64 v0 = vv.x, v1 = vv.y;
                u64 w0 = splat2(pv0), w1 = splat2(pv1);
                u64 w2 = splat2(pv2), w3 = splat2(pv3);
                ffma2(o[0][0], w0, v0); ffma2(o[0][1], w0, v1);
                ffma2(o[1][0], w1, v0); ffma2(o[1][1], w1, v1);
                ffma2(o[2][0], w2, v0); ffma2(o[2][1], w2, v1);
                ffma2(o[3][0], w3, v0); ffma2(o[3][1], w3, v1);
            }
        }
    }

#pragma unroll
    for (int qq = 0; qq < 4; qq++) {
        float inv = 1.f / lr[qq];
        float4 w;
        w.x = o[qq][0].x * inv; w.y = o[qq][0].y * inv;
        w.z = o[qq][1].x * inv; w.w = o[qq][1].y * inv;
        float* op = outp + (size_t)(b * NN + q0 + ty * 4 + qq) * CC + h * DD + tx * 4;
        *(float4*)op = w;
    }
}

// ---------------------------------------------------------------------------
extern "C" void kernel_launch(void* const* d_in, const int* in_sizes, int n_in,
                              void* d_out, int out_size) {
    const float* x      = (const float*)d_in[0];
    const float* freqs  = (const float*)d_in[1];
    const float* w_qkv  = (const float*)d_in[2];
    const float* w_proj = (const float*)d_in[3];
    const float* b_proj = (const float*)d_in[4];
    float* out = (float*)d_out;

    float *qkv, *attn;
    cudaGetSymbolAddress((void**)&qkv, g_qkv);
    cudaGetSymbolAddress((void**)&attn, g_attn);

    // 1) qkv = x @ w_qkv^T   (mma.sync bf16 split)
    gemm_mma<<<dim3(3 * CC / 128, MR / 128), 256>>>(x, w_qkv, nullptr, qkv,
                                                    MR, 3 * CC, CC);
    // 2) RoPE on q,k
    rotary_kernel<<<(BB * NN * HH * (DD / 2)) / 256, 256>>>(qkv, freqs);
    // 3) attention
    attn_kernel<<<dim3(NN / 64, HH, BB), 256>>>(qkv, attn);
    // 4) out = attn @ w_proj^T + b_proj   (mma.sync bf16 split)
    gemm_mma<<<dim3(CC / 128, MR / 128), 256>>>(attn, w_proj, b_proj, out,
                                                MR, CC, CC);
}

// round 5
// speedup vs baseline: 5.4694x; 1.6759x over previous
#include <cuda_runtime.h>
#include <cuda_bf16.h>
#include <math.h>
#include <stdint.h>

#define BB 2
#define NN 2048
#define CC 1024
#define HH 16
#define DD 64
#define MR (BB*NN)          // 4096 rows
#define QK_SCALE 0.125f     // 64^-0.5

// Scratch (allocation-free rule: device globals)
__device__ float g_qkv[(size_t)MR * 3 * CC];   // [4096][3072]  q|k|v
__device__ float g_attn[(size_t)MR * CC];      // [4096][1024]

typedef unsigned long long u64;

// ---- mma.sync helpers -----------------------------------------------------
__device__ __forceinline__ uint32_t smem_u32(const void* p) {
    return (uint32_t)__cvta_generic_to_shared(p);
}
__device__ __forceinline__ void ldmx4(uint32_t* r, uint32_t addr) {
    asm volatile("ldmatrix.sync.aligned.m8n8.x4.shared.b16 {%0,%1,%2,%3}, [%4];"
                 : "=r"(r[0]), "=r"(r[1]), "=r"(r[2]), "=r"(r[3]) : "r"(addr));
}
__device__ __forceinline__ void ldmx4t(uint32_t* r, uint32_t addr) {
    asm volatile("ldmatrix.sync.aligned.m8n8.x4.trans.shared.b16 {%0,%1,%2,%3}, [%4];"
                 : "=r"(r[0]), "=r"(r[1]), "=r"(r[2]), "=r"(r[3]) : "r"(addr));
}
__device__ __forceinline__ void mma_bf16(float* c, const uint32_t* a, const uint32_t* b) {
    asm volatile(
        "mma.sync.aligned.m16n8k16.row.col.f32.bf16.bf16.f32 "
        "{%0,%1,%2,%3}, {%4,%5,%6,%7}, {%8,%9}, {%0,%1,%2,%3};"
        : "+f"(c[0]), "+f"(c[1]), "+f"(c[2]), "+f"(c[3])
        : "r"(a[0]), "r"(a[1]), "r"(a[2]), "r"(a[3]), "r"(b[0]), "r"(b[1]));
}
__device__ __forceinline__ uint32_t pack2bf(float x, float y) {
    __nv_bfloat162 h = __floats2bfloat162_rn(x, y);
    return *(uint32_t*)&h;
}
// split (x,y) into hi/lo bf16 pairs stored at ph/pl (4-byte aligned)
__device__ __forceinline__ void split_store(__nv_bfloat16* ph, __nv_bfloat16* pl,
                                            float x, float y) {
    float hx = __bfloat162float(__float2bfloat16(x));
    float hy = __bfloat162float(__float2bfloat16(y));
    *(uint32_t*)ph = pack2bf(hx, hy);
    *(uint32_t*)pl = pack2bf(x - hx, y - hy);
}

// ---------------------------------------------------------------------------
// Tensor-core GEMM via mma.sync bf16 + hi/lo split (round-4, proven).
// ---------------------------------------------------------------------------
#define SPAD 40   // bf16 elements per smem row (32 data + 8 pad)

__global__ __launch_bounds__(256) void gemm_mma(const float* __restrict__ A,
                                                const float* __restrict__ W,
                                                const float* __restrict__ bias,
                                                float* __restrict__ Cm,
                                                int M, int Nc, int K) {
    __shared__ __nv_bfloat16 Ah[128][SPAD];
    __shared__ __nv_bfloat16 Al[128][SPAD];
    __shared__ __nv_bfloat16 Bh[128][SPAD];
    __shared__ __nv_bfloat16 Bl[128][SPAD];

    const int tid = threadIdx.x;
    const int wid = tid >> 5;
    const int lane = tid & 31;
    const int m0 = blockIdx.y * 128;
    const int n0 = blockIdx.x * 128;

    const int wm = (wid >> 2) * 64;
    const int wn = (wid & 3) * 32;

    const int lrow = tid >> 1;
    const int lcol = (tid & 1) * 16;
    const float* Ag = A + (size_t)(m0 + lrow) * K + lcol;
    const float* Wg = W + (size_t)(n0 + lrow) * K + lcol;

    float acc[4][4][4];
#pragma unroll
    for (int i = 0; i < 4; i++)
#pragma unroll
        for (int j = 0; j < 4; j++)
#pragma unroll
            for (int f = 0; f < 4; f++) acc[i][j][f] = 0.f;

    const uint32_t a_row = wm + (lane & 15);
    const uint32_t a_coff = (lane >> 4) * 8;
    const uint32_t b_row = wn + ((lane >> 4) << 3) + (lane & 7);
    const uint32_t b_coff = ((lane >> 3) & 1) * 8;

    const uint32_t sAh = smem_u32(Ah), sAl = smem_u32(Al);
    const uint32_t sBh = smem_u32(Bh), sBl = smem_u32(Bl);

    for (int k0 = 0; k0 < K; k0 += 32) {
#pragma unroll
        for (int j = 0; j < 16; j += 4) {
            float4 va = *(const float4*)(Ag + k0 + j);
            float4 vb = *(const float4*)(Wg + k0 + j);
            int c = lcol + j;
            split_store(&Ah[lrow][c], &Al[lrow][c], va.x, va.y);
            split_store(&Ah[lrow][c + 2], &Al[lrow][c + 2], va.z, va.w);
            split_store(&Bh[lrow][c], &Bl[lrow][c], vb.x, vb.y);
            split_store(&Bh[lrow][c + 2], &Bl[lrow][c + 2], vb.z, vb.w);
        }
        __syncthreads();

#pragma unroll
        for (int ks = 0; ks < 2; ks++) {
            const uint32_t kc = ks * 16;
            uint32_t afh[4][4], afl[4][4];
#pragma unroll
            for (int mt = 0; mt < 4; mt++) {
                uint32_t off = ((a_row + mt * 16) * SPAD + kc + a_coff) * 2;
                ldmx4(afh[mt], sAh + off);
                ldmx4(afl[mt], sAl + off);
            }
            uint32_t bfh[2][4], bfl[2][4];
#pragma unroll
            for (int bt = 0; bt < 2; bt++) {
                uint32_t off = ((b_row + bt * 16) * SPAD + kc + b_coff) * 2;
                ldmx4(bfh[bt], sBh + off);
                ldmx4(bfl[bt], sBl + off);
            }
#pragma unroll
            for (int mt = 0; mt < 4; mt++)
#pragma unroll
                for (int nt = 0; nt < 4; nt++) {
                    uint32_t* bh = &bfh[nt >> 1][(nt & 1) * 2];
                    uint32_t* bl = &bfl[nt >> 1][(nt & 1) * 2];
                    mma_bf16(acc[mt][nt], afh[mt], bh);
                    mma_bf16(acc[mt][nt], afh[mt], bl);
                    mma_bf16(acc[mt][nt], afl[mt], bh);
                }
        }
        __syncthreads();
    }

    const int erow = lane >> 2;
    const int ecol = (lane & 3) * 2;
#pragma unroll
    for (int mt = 0; mt < 4; mt++) {
#pragma unroll
        for (int nt = 0; nt < 4; nt++) {
            int gr = m0 + wm + mt * 16 + erow;
            int gc = n0 + wn + nt * 8 + ecol;
            float b0 = 0.f, b1 = 0.f;
            if (bias) { b0 = bias[gc]; b1 = bias[gc + 1]; }
            float2 v0 = make_float2(acc[mt][nt][0] + b0, acc[mt][nt][1] + b1);
            float2 v1 = make_float2(acc[mt][nt][2] + b0, acc[mt][nt][3] + b1);
            *(float2*)(Cm + (size_t)gr * Nc + gc) = v0;
            *(float2*)(Cm + (size_t)(gr + 8) * Nc + gc) = v1;
        }
    }
}

// ---------------------------------------------------------------------------
// Flash attention on mma.sync bf16 (hi/lo split), RoPE fused into staging.
// CTA: 128 q-rows x one head x one batch, 8 warps (16 q-rows each).
// k-block = 64 keys. S = Q.K^T and O += P.V, both 3-term split MMAs.
// smem overlay: [Qh|Ql] (phase 1) reused as [Kh|Kl|Vh|Vl] (steady state).
// ---------------------------------------------------------------------------
#define APAD 72   // bf16 elems per smem row (64 data + 8 pad)

__global__ __launch_bounds__(256, 1) void attn_mma(const float* __restrict__ qkv,
                                                   const float* __restrict__ freqs,
                                                   float* __restrict__ outp) {
    __shared__ __align__(16) char sm_raw[4 * 64 * APAD * 2];   // 36864 B

    __nv_bfloat16* const Qh = (__nv_bfloat16*)sm_raw;          // [128][APAD]
    __nv_bfloat16* const Ql = Qh + 128 * APAD;
    __nv_bfloat16* const Kh = (__nv_bfloat16*)sm_raw;          // [64][APAD]
    __nv_bfloat16* const Kl = Kh + 64 * APAD;
    __nv_bfloat16* const Vh = Kl + 64 * APAD;
    __nv_bfloat16* const Vl = Vh + 64 * APAD;

    const int t = threadIdx.x;
    const int wid = t >> 5;
    const int lane = t & 31;
    const int h = blockIdx.y;
    const int b = blockIdx.z;
    const int q0 = blockIdx.x * 128;
    const size_t rstride = 3 * CC;

    // ---- stage Q: RoPE + scale + hi/lo split ----
    {
        int row = t >> 1, half = (t & 1) * 32;
        const float* qp = qkv + (size_t)(b * NN + q0 + row) * rstride + h * DD + half;
        const float* fp = freqs + (size_t)(q0 + row) * (DD / 2) + half / 2;
#pragma unroll
        for (int j = 0; j < 32; j += 4) {
            float4 v = *(const float4*)(qp + j);
            float c0, s0, c1, s1;
            __sincosf(fp[j / 2], &s0, &c0);
            __sincosf(fp[j / 2 + 1], &s1, &c1);
            float r0 = (v.x * c0 - v.y * s0) * QK_SCALE;
            float r1 = (v.x * s0 + v.y * c0) * QK_SCALE;
            float r2 = (v.z * c1 - v.w * s1) * QK_SCALE;
            float r3 = (v.z * s1 + v.w * c1) * QK_SCALE;
            split_store(&Qh[row * APAD + half + j], &Ql[row * APAD + half + j], r0, r1);
            split_store(&Qh[row * APAD + half + j + 2], &Ql[row * APAD + half + j + 2], r2, r3);
        }
    }
    __syncthreads();

    // ---- Q fragments to registers (held for whole kernel) ----
    uint32_t qfh[4][4], qfl[4][4];
    {
        const uint32_t arow = wid * 16 + (lane & 15);
        const uint32_t acoff = (lane >> 4) * 8;
        const uint32_t sQh = smem_u32(Qh), sQl = smem_u32(Ql);
#pragma unroll
        for (int ks = 0; ks < 4; ks++) {
            uint32_t off = (arow * APAD + ks * 16 + acoff) * 2;
            ldmx4(qfh[ks], sQh + off);
            ldmx4(qfl[ks], sQl + off);
        }
    }

    float o[8][4];
#pragma unroll
    for (int i = 0; i < 8; i++)
#pragma unroll
        for (int f = 0; f < 4; f++) o[i][f] = 0.f;
    float m0 = -1e30f, m1 = -1e30f, l0 = 0.f, l1 = 0.f;

    const uint32_t sKh = smem_u32(Kh), sKl = smem_u32(Kl);
    const uint32_t sVh = smem_u32(Vh), sVl = smem_u32(Vl);
    const uint32_t b_row = ((lane >> 4) << 3) + (lane & 7);
    const uint32_t b_coff = ((lane >> 3) & 1) * 8;
    const uint32_t v_row = ((lane >> 3) & 1) * 8 + (lane & 7);
    const uint32_t v_coff = (lane >> 4) * 8;

    for (int kt = 0; kt < NN / 64; kt++) {
        __syncthreads();   // previous block's fragments consumed; smem reusable
        {   // ---- stage K (RoPE) and V, split ----
            int row = t >> 2, dseg = (t & 3) * 16;
            const float* kp = qkv + (size_t)(b * NN + kt * 64 + row) * rstride
                              + CC + h * DD + dseg;
            const float* vp = kp + CC;
            const float* fp = freqs + (size_t)(kt * 64 + row) * (DD / 2) + dseg / 2;
#pragma unroll
            for (int j = 0; j < 16; j += 4) {
                float4 kv = *(const float4*)(kp + j);
                float c0, s0, c1, s1;
                __sincosf(fp[j / 2], &s0, &c0);
                __sincosf(fp[j / 2 + 1], &s1, &c1);
                float r0 = kv.x * c0 - kv.y * s0;
                float r1 = kv.x * s0 + kv.y * c0;
                float r2 = kv.z * c1 - kv.w * s1;
                float r3 = kv.z * s1 + kv.w * c1;
                split_store(&Kh[row * APAD + dseg + j], &Kl[row * APAD + dseg + j], r0, r1);
                split_store(&Kh[row * APAD + dseg + j + 2], &Kl[row * APAD + dseg + j + 2], r2, r3);
                float4 vv = *(const float4*)(vp + j);
                split_store(&Vh[row * APAD + dseg + j], &Vl[row * APAD + dseg + j], vv.x, vv.y);
                split_store(&Vh[row * APAD + dseg + j + 2], &Vl[row * APAD + dseg + j + 2], vv.z, vv.w);
            }
        }
        __syncthreads();

        // ---- S = Q.K^T : 8 n-tiles (64 keys), 4 k-steps (d=64), split ----
        float s[8][4];
#pragma unroll
        for (int i = 0; i < 8; i++)
#pragma unroll
            for (int f = 0; f < 4; f++) s[i][f] = 0.f;
#pragma unroll
        for (int ks = 0; ks < 4; ks++) {
            const uint32_t kc = ks * 16;
#pragma unroll
            for (int g = 0; g < 4; g++) {
                uint32_t bh[4], bl[4];
                uint32_t off = ((g * 16 + b_row) * APAD + kc + b_coff) * 2;
                ldmx4(bh, sKh + off);
                ldmx4(bl, sKl + off);
                mma_bf16(s[2 * g],     qfh[ks], &bh[0]);
                mma_bf16(s[2 * g],     qfh[ks], &bl[0]);
                mma_bf16(s[2 * g],     qfl[ks], &bh[0]);
                mma_bf16(s[2 * g + 1], qfh[ks], &bh[2]);
                mma_bf16(s[2 * g + 1], qfh[ks], &bl[2]);
                mma_bf16(s[2 * g + 1], qfl[ks], &bh[2]);
            }
        }

        // ---- online softmax (rows r = lane>>2 and r+8) ----
        float tm0 = -1e30f, tm1 = -1e30f;
#pragma unroll
        for (int nt = 0; nt < 8; nt++) {
            tm0 = fmaxf(tm0, fmaxf(s[nt][0], s[nt][1]));
            tm1 = fmaxf(tm1, fmaxf(s[nt][2], s[nt][3]));
        }
        tm0 = fmaxf(tm0, __shfl_xor_sync(0xffffffffu, tm0, 1));
        tm0 = fmaxf(tm0, __shfl_xor_sync(0xffffffffu, tm0, 2));
        tm1 = fmaxf(tm1, __shfl_xor_sync(0xffffffffu, tm1, 1));
        tm1 = fmaxf(tm1, __shfl_xor_sync(0xffffffffu, tm1, 2));
        float mn0 = fmaxf(m0, tm0), mn1 = fmaxf(m1, tm1);
        float al0 = __expf(m0 - mn0), al1 = __expf(m1 - mn1);
        m0 = mn0; m1 = mn1;
        float rs0 = 0.f, rs1 = 0.f;
#pragma unroll
        for (int nt = 0; nt < 8; nt++) {
            s[nt][0] = __expf(s[nt][0] - m0);
            s[nt][1] = __expf(s[nt][1] - m0);
            s[nt][2] = __expf(s[nt][2] - m1);
            s[nt][3] = __expf(s[nt][3] - m1);
            rs0 += s[nt][0] + s[nt][1];
            rs1 += s[nt][2] + s[nt][3];
        }
        rs0 += __shfl_xor_sync(0xffffffffu, rs0, 1);
        rs0 += __shfl_xor_sync(0xffffffffu, rs0, 2);
        rs1 += __shfl_xor_sync(0xffffffffu, rs1, 1);
        rs1 += __shfl_xor_sync(0xffffffffu, rs1, 2);
        l0 = l0 * al0 + rs0;
        l1 = l1 * al1 + rs1;
#pragma unroll
        for (int nt = 0; nt < 8; nt++) {
            o[nt][0] *= al0; o[nt][1] *= al0;
            o[nt][2] *= al1; o[nt][3] *= al1;
        }

        // ---- pack P into A-fragments (hi/lo) straight from S registers ----
        uint32_t ph[4][4], pl[4][4];
#pragma unroll
        for (int ks = 0; ks < 4; ks++) {
#pragma unroll
            for (int hf = 0; hf < 2; hf++) {
                int nt = 2 * ks + hf;
                float p0 = s[nt][0], p1 = s[nt][1], p2 = s[nt][2], p3 = s[nt][3];
                float h0 = __bfloat162float(__float2bfloat16(p0));
                float h1 = __bfloat162float(__float2bfloat16(p1));
                float h2 = __bfloat162float(__float2bfloat16(p2));
                float h3 = __bfloat162float(__float2bfloat16(p3));
                ph[ks][hf * 2 + 0] = pack2bf(h0, h1);
                ph[ks][hf * 2 + 1] = pack2bf(h2, h3);
                pl[ks][hf * 2 + 0] = pack2bf(p0 - h0, p1 - h1);
                pl[ks][hf * 2 + 1] = pack2bf(p2 - h2, p3 - h3);
            }
        }

        // ---- O += P.V : B-fragments via ldmatrix.trans from V[key][d] ----
#pragma unroll
        for (int ks = 0; ks < 4; ks++) {
            const uint32_t krow = ks * 16 + v_row;
#pragma unroll
            for (int g = 0; g < 4; g++) {
                uint32_t vh4[4], vl4[4];
                uint32_t off = (krow * APAD + g * 16 + v_coff) * 2;
                ldmx4t(vh4, sVh + off);
                ldmx4t(vl4, sVl + off);
                mma_bf16(o[2 * g],     ph[ks], &vh4[0]);
                mma_bf16(o[2 * g],     ph[ks], &vl4[0]);
                mma_bf16(o[2 * g],     pl[ks], &vh4[0]);
                mma_bf16(o[2 * g + 1], ph[ks], &vh4[2]);
                mma_bf16(o[2 * g + 1], ph[ks], &vl4[2]);
                mma_bf16(o[2 * g + 1], pl[ks], &vh4[2]);
            }
        }
    }

    // ---- epilogue ----
    float inv0 = 1.f / l0, inv1 = 1.f / l1;
    int r0 = q0 + wid * 16 + (lane >> 2);
    int cbase = (lane & 3) * 2;
    float* op0 = outp + (size_t)(b * NN + r0) * CC + h * DD;
    float* op1 = op0 + 8 * CC;
#pragma unroll
    for (int nt = 0; nt < 8; nt++) {
        *(float2*)(op0 + nt * 8 + cbase) =
            make_float2(o[nt][0] * inv0, o[nt][1] * inv0);
        *(float2*)(op1 + nt * 8 + cbase) =
            make_float2(o[nt][2] * inv1, o[nt][3] * inv1);
    }
}

// ---------------------------------------------------------------------------
extern "C" void kernel_launch(void* const* d_in, const int* in_sizes, int n_in,
                              void* d_out, int out_size) {
    const float* x      = (const float*)d_in[0];
    const float* freqs  = (const float*)d_in[1];
    const float* w_qkv  = (const float*)d_in[2];
    const float* w_proj = (const float*)d_in[3];
    const float* b_proj = (const float*)d_in[4];
    float* out = (float*)d_out;

    float *qkv, *attn;
    cudaGetSymbolAddress((void**)&qkv, g_qkv);
    cudaGetSymbolAddress((void**)&attn, g_attn);

    // 1) qkv = x @ w_qkv^T   (mma.sync bf16 split)
    gemm_mma<<<dim3(3 * CC / 128, MR / 128), 256>>>(x, w_qkv, nullptr, qkv,
                                                    MR, 3 * CC, CC);
    // 2) attention (RoPE fused into Q/K staging)
    attn_mma<<<dim3(NN / 128, HH, BB), 256>>>(qkv, freqs, attn);
    // 3) out = attn @ w_proj^T + b_proj   (mma.sync bf16 split)
    gemm_mma<<<dim3(CC / 128, MR / 128), 256>>>(attn, w_proj, b_proj, out,
                                                MR, CC, CC);
}

// round 6
// speedup vs baseline: 6.1200x; 1.1190x over previous
#include <cuda_runtime.h>
#include <cuda_bf16.h>
#include <math.h>
#include <stdint.h>

#define BB 2
#define NN 2048
#define CC 1024
#define HH 16
#define DD 64
#define MR (BB*NN)          // 4096 rows
#define QK_SCALE 0.125f     // 64^-0.5

// ---- global scratch (allocation-free rule) --------------------------------
__device__ float g_qkv[(size_t)MR * 3 * CC];                  // fp32 qkv
__device__ __nv_bfloat16 g_xh[(size_t)MR * CC],  g_xl[(size_t)MR * CC];
__device__ __nv_bfloat16 g_wqh[(size_t)3 * CC * CC], g_wql[(size_t)3 * CC * CC];
__device__ __nv_bfloat16 g_wph[(size_t)CC * CC], g_wpl[(size_t)CC * CC];
__device__ __nv_bfloat16 g_ah[(size_t)MR * CC],  g_al[(size_t)MR * CC];
// RoPE'd, split, head-contiguous [b][h][n][64]
__device__ __nv_bfloat16 g_Qh[(size_t)MR * CC], g_Ql[(size_t)MR * CC];
__device__ __nv_bfloat16 g_Kh[(size_t)MR * CC], g_Kl[(size_t)MR * CC];
__device__ __nv_bfloat16 g_Vh[(size_t)MR * CC], g_Vl[(size_t)MR * CC];

// ---- mma.sync helpers -----------------------------------------------------
__device__ __forceinline__ uint32_t smem_u32(const void* p) {
    return (uint32_t)__cvta_generic_to_shared(p);
}
__device__ __forceinline__ void ldmx4(uint32_t* r, uint32_t addr) {
    asm volatile("ldmatrix.sync.aligned.m8n8.x4.shared.b16 {%0,%1,%2,%3}, [%4];"
                 : "=r"(r[0]), "=r"(r[1]), "=r"(r[2]), "=r"(r[3]) : "r"(addr));
}
__device__ __forceinline__ void ldmx4t(uint32_t* r, uint32_t addr) {
    asm volatile("ldmatrix.sync.aligned.m8n8.x4.trans.shared.b16 {%0,%1,%2,%3}, [%4];"
                 : "=r"(r[0]), "=r"(r[1]), "=r"(r[2]), "=r"(r[3]) : "r"(addr));
}
__device__ __forceinline__ void mma_bf16(float* c, const uint32_t* a, const uint32_t* b) {
    asm volatile(
        "mma.sync.aligned.m16n8k16.row.col.f32.bf16.bf16.f32 "
        "{%0,%1,%2,%3}, {%4,%5,%6,%7}, {%8,%9}, {%0,%1,%2,%3};"
        : "+f"(c[0]), "+f"(c[1]), "+f"(c[2]), "+f"(c[3])
        : "r"(a[0]), "r"(a[1]), "r"(a[2]), "r"(a[3]), "r"(b[0]), "r"(b[1]));
}
__device__ __forceinline__ uint32_t pack2bf(float x, float y) {
    __nv_bfloat162 h = __floats2bfloat162_rn(x, y);
    return *(uint32_t*)&h;
}
__device__ __forceinline__ void split2(float x, float y, uint32_t& hi, uint32_t& lo) {
    float hx = __bfloat162float(__float2bfloat16(x));
    float hy = __bfloat162float(__float2bfloat16(y));
    hi = pack2bf(hx, hy);
    lo = pack2bf(x - hx, y - hy);
}

// ---------------------------------------------------------------------------
// split fp32 -> hi/lo bf16 (vectorized by 4)
// ---------------------------------------------------------------------------
__global__ void split_kernel(const float* __restrict__ src,
                             __nv_bfloat16* __restrict__ hi,
                             __nv_bfloat16* __restrict__ lo, int n4) {
    int i = blockIdx.x * blockDim.x + threadIdx.x;
    if (i >= n4) return;
    float4 v = ((const float4*)src)[i];
    uint32_t h0, l0, h1, l1;
    split2(v.x, v.y, h0, l0);
    split2(v.z, v.w, h1, l1);
    ((uint2*)hi)[i] = make_uint2(h0, h1);
    ((uint2*)lo)[i] = make_uint2(h0 = l0, l1);   // (h0 reused as temp)
}

// ---------------------------------------------------------------------------
// prep: read fp32 qkv, RoPE q/k (+scale q), split q/k/v into [b][h][n][64]
// 2 threads per (b,h,n) row, 32 d each.
// ---------------------------------------------------------------------------
__global__ void prep_qkv(const float* __restrict__ qkv,
                         const float* __restrict__ freqs) {
    int gid = blockIdx.x * blockDim.x + threadIdx.x;   // 131072 total
    int half = gid & 1;
    int h = (gid >> 1) & (HH - 1);
    int n = (gid >> 5) & (NN - 1);
    int b = gid >> 16;

    const float* base = qkv + (size_t)(b * NN + n) * 3 * CC + h * DD + half * 32;
    const float* fp = freqs + (size_t)n * 32 + half * 16;
    size_t orow = ((size_t)(b * HH + h) * NN + n) * 64 + half * 32;

#pragma unroll
    for (int j = 0; j < 32; j += 4) {
        float c0, s0, c1, s1;
        __sincosf(fp[j / 2], &s0, &c0);
        __sincosf(fp[j / 2 + 1], &s1, &c1);
        uint32_t hi0, lo0, hi1, lo1;

        float4 q = *(const float4*)(base + j);
        split2((q.x * c0 - q.y * s0) * QK_SCALE, (q.x * s0 + q.y * c0) * QK_SCALE, hi0, lo0);
        split2((q.z * c1 - q.w * s1) * QK_SCALE, (q.z * s1 + q.w * c1) * QK_SCALE, hi1, lo1);
        *(uint2*)(g_Qh + orow + j) = make_uint2(hi0, hi1);
        *(uint2*)(g_Ql + orow + j) = make_uint2(lo0, lo1);

        float4 k = *(const float4*)(base + CC + j);
        split2(k.x * c0 - k.y * s0, k.x * s0 + k.y * c0, hi0, lo0);
        split2(k.z * c1 - k.w * s1, k.z * s1 + k.w * c1, hi1, lo1);
        *(uint2*)(g_Kh + orow + j) = make_uint2(hi0, hi1);
        *(uint2*)(g_Kl + orow + j) = make_uint2(lo0, lo1);

        float4 v = *(const float4*)(base + 2 * CC + j);
        split2(v.x, v.y, hi0, lo0);
        split2(v.z, v.w, hi1, lo1);
        *(uint2*)(g_Vh + orow + j) = make_uint2(hi0, hi1);
        *(uint2*)(g_Vl + orow + j) = make_uint2(lo0, lo1);
    }
}

// ---------------------------------------------------------------------------
// GEMM on pre-split bf16 inputs: Cm = A @ W^T (+bias), fp32 out.
// CTA 128x128, K-chunk 32, 8 warps (64x32 warp tile), 3-term split MMAs.
// ---------------------------------------------------------------------------
#define SPAD 40

__global__ __launch_bounds__(256, 2) void gemm_b16(
        const __nv_bfloat16* __restrict__ Ahg, const __nv_bfloat16* __restrict__ Alg,
        const __nv_bfloat16* __restrict__ Whg, const __nv_bfloat16* __restrict__ Wlg,
        const float* __restrict__ bias, float* __restrict__ Cm,
        int M, int Nc, int K) {
    __shared__ __nv_bfloat16 Ah[128][SPAD];
    __shared__ __nv_bfloat16 Al[128][SPAD];
    __shared__ __nv_bfloat16 Bh[128][SPAD];
    __shared__ __nv_bfloat16 Bl[128][SPAD];

    const int tid = threadIdx.x;
    const int wid = tid >> 5;
    const int lane = tid & 31;
    const int m0 = blockIdx.y * 128;
    const int n0 = blockIdx.x * 128;
    const int wm = (wid >> 2) * 64;
    const int wn = (wid & 3) * 32;

    const int lrow = tid >> 1;
    const int lcol = (tid & 1) * 16;
    const __nv_bfloat16* Ahp = Ahg + (size_t)(m0 + lrow) * K + lcol;
    const __nv_bfloat16* Alp = Alg + (size_t)(m0 + lrow) * K + lcol;
    const __nv_bfloat16* Whp = Whg + (size_t)(n0 + lrow) * K + lcol;
    const __nv_bfloat16* Wlp = Wlg + (size_t)(n0 + lrow) * K + lcol;

    float acc[4][4][4];
#pragma unroll
    for (int i = 0; i < 4; i++)
#pragma unroll
        for (int j = 0; j < 4; j++)
#pragma unroll
            for (int f = 0; f < 4; f++) acc[i][j][f] = 0.f;

    const uint32_t a_row = wm + (lane & 15);
    const uint32_t a_coff = (lane >> 4) * 8;
    const uint32_t b_row = wn + ((lane >> 4) << 3) + (lane & 7);
    const uint32_t b_coff = ((lane >> 3) & 1) * 8;

    const uint32_t sAh = smem_u32(Ah), sAl = smem_u32(Al);
    const uint32_t sBh = smem_u32(Bh), sBl = smem_u32(Bl);

    for (int k0 = 0; k0 < K; k0 += 32) {
        *(uint4*)&Ah[lrow][lcol]     = *(const uint4*)(Ahp + k0);
        *(uint4*)&Ah[lrow][lcol + 8] = *(const uint4*)(Ahp + k0 + 8);
        *(uint4*)&Al[lrow][lcol]     = *(const uint4*)(Alp + k0);
        *(uint4*)&Al[lrow][lcol + 8] = *(const uint4*)(Alp + k0 + 8);
        *(uint4*)&Bh[lrow][lcol]     = *(const uint4*)(Whp + k0);
        *(uint4*)&Bh[lrow][lcol + 8] = *(const uint4*)(Whp + k0 + 8);
        *(uint4*)&Bl[lrow][lcol]     = *(const uint4*)(Wlp + k0);
        *(uint4*)&Bl[lrow][lcol + 8] = *(const uint4*)(Wlp + k0 + 8);
        __syncthreads();

#pragma unroll
        for (int ks = 0; ks < 2; ks++) {
            const uint32_t kc = ks * 16;
            uint32_t afh[4][4], afl[4][4];
#pragma unroll
            for (int mt = 0; mt < 4; mt++) {
                uint32_t off = ((a_row + mt * 16) * SPAD + kc + a_coff) * 2;
                ldmx4(afh[mt], sAh + off);
                ldmx4(afl[mt], sAl + off);
            }
            uint32_t bfh[2][4], bfl[2][4];
#pragma unroll
            for (int bt = 0; bt < 2; bt++) {
                uint32_t off = ((b_row + bt * 16) * SPAD + kc + b_coff) * 2;
                ldmx4(bfh[bt], sBh + off);
                ldmx4(bfl[bt], sBl + off);
            }
#pragma unroll
            for (int mt = 0; mt < 4; mt++)
#pragma unroll
                for (int nt = 0; nt < 4; nt++) {
                    uint32_t* bh = &bfh[nt >> 1][(nt & 1) * 2];
                    uint32_t* bl = &bfl[nt >> 1][(nt & 1) * 2];
                    mma_bf16(acc[mt][nt], afh[mt], bh);
                    mma_bf16(acc[mt][nt], afh[mt], bl);
                    mma_bf16(acc[mt][nt], afl[mt], bh);
                }
        }
        __syncthreads();
    }

    const int erow = lane >> 2;
    const int ecol = (lane & 3) * 2;
#pragma unroll
    for (int mt = 0; mt < 4; mt++) {
#pragma unroll
        for (int nt = 0; nt < 4; nt++) {
            int gr = m0 + wm + mt * 16 + erow;
            int gc = n0 + wn + nt * 8 + ecol;
            float b0 = 0.f, b1 = 0.f;
            if (bias) { b0 = bias[gc]; b1 = bias[gc + 1]; }
            *(float2*)(Cm + (size_t)gr * Nc + gc) =
                make_float2(acc[mt][nt][0] + b0, acc[mt][nt][1] + b1);
            *(float2*)(Cm + (size_t)(gr + 8) * Nc + gc) =
                make_float2(acc[mt][nt][2] + b0, acc[mt][nt][3] + b1);
        }
    }
}

// ---------------------------------------------------------------------------
// Flash attention on pre-split bf16 Q/K/V. Staging = pure copies.
// CTA: 128 q-rows x head x batch, 8 warps. Output written pre-split (ah/al).
// ---------------------------------------------------------------------------
#define APAD 72

__global__ __launch_bounds__(256, 1) void attn_mma(void) {
    __shared__ __align__(16) char sm_raw[4 * 64 * APAD * 2];   // 36864 B

    __nv_bfloat16* const Qh = (__nv_bfloat16*)sm_raw;          // [128][APAD]
    __nv_bfloat16* const Ql = Qh + 128 * APAD;
    __nv_bfloat16* const Kh = (__nv_bfloat16*)sm_raw;          // [64][APAD]
    __nv_bfloat16* const Kl = Kh + 64 * APAD;
    __nv_bfloat16* const Vh = Kl + 64 * APAD;
    __nv_bfloat16* const Vl = Vh + 64 * APAD;

    const int t = threadIdx.x;
    const int wid = t >> 5;
    const int lane = t & 31;
    const int h = blockIdx.y;
    const int b = blockIdx.z;
    const int q0 = blockIdx.x * 128;

    const size_t hbase = (size_t)(b * HH + h) * NN * 64;

    // ---- stage Q (plain copy of pre-RoPE'd, pre-scaled split data) ----
    {
        int row = t >> 1, half = (t & 1) * 32;
        size_t src = hbase + (size_t)(q0 + row) * 64 + half;
        size_t dst = (size_t)row * APAD + half;
#pragma unroll
        for (int j = 0; j < 32; j += 8) {
            *(uint4*)(Qh + dst + j) = *(const uint4*)(g_Qh + src + j);
            *(uint4*)(Ql + dst + j) = *(const uint4*)(g_Ql + src + j);
        }
    }
    __syncthreads();

    // ---- Q fragments to registers ----
    uint32_t qfh[4][4], qfl[4][4];
    {
        const uint32_t arow = wid * 16 + (lane & 15);
        const uint32_t acoff = (lane >> 4) * 8;
        const uint32_t sQh = smem_u32(Qh), sQl = smem_u32(Ql);
#pragma unroll
        for (int ks = 0; ks < 4; ks++) {
            uint32_t off = (arow * APAD + ks * 16 + acoff) * 2;
            ldmx4(qfh[ks], sQh + off);
            ldmx4(qfl[ks], sQl + off);
        }
    }

    float o[8][4];
#pragma unroll
    for (int i = 0; i < 8; i++)
#pragma unroll
        for (int f = 0; f < 4; f++) o[i][f] = 0.f;
    float m0 = -1e30f, m1 = -1e30f, l0 = 0.f, l1 = 0.f;

    const uint32_t sKh = smem_u32(Kh), sKl = smem_u32(Kl);
    const uint32_t sVh = smem_u32(Vh), sVl = smem_u32(Vl);
    const uint32_t b_row = ((lane >> 4) << 3) + (lane & 7);
    const uint32_t b_coff = ((lane >> 3) & 1) * 8;
    const uint32_t v_row = ((lane >> 3) & 1) * 8 + (lane & 7);
    const uint32_t v_coff = (lane >> 4) * 8;

    for (int kt = 0; kt < NN / 64; kt++) {
        __syncthreads();
        {   // ---- stage K/V: pure copies ----
            int row = t >> 2, c16 = (t & 3) * 16;
            size_t src = hbase + (size_t)(kt * 64 + row) * 64 + c16;
            size_t dst = (size_t)row * APAD + c16;
            *(uint4*)(Kh + dst)     = *(const uint4*)(g_Kh + src);
            *(uint4*)(Kh + dst + 8) = *(const uint4*)(g_Kh + src + 8);
            *(uint4*)(Kl + dst)     = *(const uint4*)(g_Kl + src);
            *(uint4*)(Kl + dst + 8) = *(const uint4*)(g_Kl + src + 8);
            *(uint4*)(Vh + dst)     = *(const uint4*)(g_Vh + src);
            *(uint4*)(Vh + dst + 8) = *(const uint4*)(g_Vh + src + 8);
            *(uint4*)(Vl + dst)     = *(const uint4*)(g_Vl + src);
            *(uint4*)(Vl + dst + 8) = *(const uint4*)(g_Vl + src + 8);
        }
        __syncthreads();

        // ---- S = Q.K^T ----
        float s[8][4];
#pragma unroll
        for (int i = 0; i < 8; i++)
#pragma unroll
            for (int f = 0; f < 4; f++) s[i][f] = 0.f;
#pragma unroll
        for (int ks = 0; ks < 4; ks++) {
            const uint32_t kc = ks * 16;
#pragma unroll
            for (int g = 0; g < 4; g++) {
                uint32_t bh[4], bl[4];
                uint32_t off = ((g * 16 + b_row) * APAD + kc + b_coff) * 2;
                ldmx4(bh, sKh + off);
                ldmx4(bl, sKl + off);
                mma_bf16(s[2 * g],     qfh[ks], &bh[0]);
                mma_bf16(s[2 * g],     qfh[ks], &bl[0]);
                mma_bf16(s[2 * g],     qfl[ks], &bh[0]);
                mma_bf16(s[2 * g + 1], qfh[ks], &bh[2]);
                mma_bf16(s[2 * g + 1], qfh[ks], &bl[2]);
                mma_bf16(s[2 * g + 1], qfl[ks], &bh[2]);
            }
        }

        // ---- online softmax ----
        float tm0 = -1e30f, tm1 = -1e30f;
#pragma unroll
        for (int nt = 0; nt < 8; nt++) {
            tm0 = fmaxf(tm0, fmaxf(s[nt][0], s[nt][1]));
            tm1 = fmaxf(tm1, fmaxf(s[nt][2], s[nt][3]));
        }
        tm0 = fmaxf(tm0, __shfl_xor_sync(0xffffffffu, tm0, 1));
        tm0 = fmaxf(tm0, __shfl_xor_sync(0xffffffffu, tm0, 2));
        tm1 = fmaxf(tm1, __shfl_xor_sync(0xffffffffu, tm1, 1));
        tm1 = fmaxf(tm1, __shfl_xor_sync(0xffffffffu, tm1, 2));
        float mn0 = fmaxf(m0, tm0), mn1 = fmaxf(m1, tm1);
        float al0 = __expf(m0 - mn0), al1 = __expf(m1 - mn1);
        m0 = mn0; m1 = mn1;
        float rs0 = 0.f, rs1 = 0.f;
#pragma unroll
        for (int nt = 0; nt < 8; nt++) {
            s[nt][0] = __expf(s[nt][0] - m0);
            s[nt][1] = __expf(s[nt][1] - m0);
            s[nt][2] = __expf(s[nt][2] - m1);
            s[nt][3] = __expf(s[nt][3] - m1);
            rs0 += s[nt][0] + s[nt][1];
            rs1 += s[nt][2] + s[nt][3];
        }
        rs0 += __shfl_xor_sync(0xffffffffu, rs0, 1);
        rs0 += __shfl_xor_sync(0xffffffffu, rs0, 2);
        rs1 += __shfl_xor_sync(0xffffffffu, rs1, 1);
        rs1 += __shfl_xor_sync(0xffffffffu, rs1, 2);
        l0 = l0 * al0 + rs0;
        l1 = l1 * al1 + rs1;
#pragma unroll
        for (int nt = 0; nt < 8; nt++) {
            o[nt][0] *= al0; o[nt][1] *= al0;
            o[nt][2] *= al1; o[nt][3] *= al1;
        }

        // ---- pack P hi/lo from registers ----
        uint32_t ph[4][4], pl[4][4];
#pragma unroll
        for (int ks = 0; ks < 4; ks++) {
#pragma unroll
            for (int hf = 0; hf < 2; hf++) {
                int nt = 2 * ks + hf;
                split2(s[nt][0], s[nt][1], ph[ks][hf * 2 + 0], pl[ks][hf * 2 + 0]);
                split2(s[nt][2], s[nt][3], ph[ks][hf * 2 + 1], pl[ks][hf * 2 + 1]);
            }
        }

        // ---- O += P.V ----
#pragma unroll
        for (int ks = 0; ks < 4; ks++) {
            const uint32_t krow = ks * 16 + v_row;
#pragma unroll
            for (int g = 0; g < 4; g++) {
                uint32_t vh4[4], vl4[4];
                uint32_t off = (krow * APAD + g * 16 + v_coff) * 2;
                ldmx4t(vh4, sVh + off);
                ldmx4t(vl4, sVl + off);
                mma_bf16(o[2 * g],     ph[ks], &vh4[0]);
                mma_bf16(o[2 * g],     ph[ks], &vl4[0]);
                mma_bf16(o[2 * g],     pl[ks], &vh4[0]);
                mma_bf16(o[2 * g + 1], ph[ks], &vh4[2]);
                mma_bf16(o[2 * g + 1], ph[ks], &vl4[2]);
                mma_bf16(o[2 * g + 1], pl[ks], &vh4[2]);
            }
        }
    }

    // ---- epilogue: write output pre-split into g_ah/g_al ----
    float inv0 = 1.f / l0, inv1 = 1.f / l1;
    int r0 = q0 + wid * 16 + (lane >> 2);
    int cbase = (lane & 3) * 2;
    size_t base0 = (size_t)(b * NN + r0) * CC + h * DD + cbase;
    size_t base1 = base0 + (size_t)8 * CC;
#pragma unroll
    for (int nt = 0; nt < 8; nt++) {
        uint32_t hi, lo;
        split2(o[nt][0] * inv0, o[nt][1] * inv0, hi, lo);
        *(uint32_t*)(g_ah + base0 + nt * 8) = hi;
        *(uint32_t*)(g_al + base0 + nt * 8) = lo;
        split2(o[nt][2] * inv1, o[nt][3] * inv1, hi, lo);
        *(uint32_t*)(g_ah + base1 + nt * 8) = hi;
        *(uint32_t*)(g_al + base1 + nt * 8) = lo;
    }
}

// ---------------------------------------------------------------------------
extern "C" void kernel_launch(void* const* d_in, const int* in_sizes, int n_in,
                              void* d_out, int out_size) {
    const float* x      = (const float*)d_in[0];
    const float* freqs  = (const float*)d_in[1];
    const float* w_qkv  = (const float*)d_in[2];
    const float* w_proj = (const float*)d_in[3];
    const float* b_proj = (const float*)d_in[4];
    float* out = (float*)d_out;

    float* qkv;
    cudaGetSymbolAddress((void**)&qkv, g_qkv);
    __nv_bfloat16 *xh, *xl, *wqh, *wql, *wph, *wpl, *ah, *al;
    cudaGetSymbolAddress((void**)&xh, g_xh);
    cudaGetSymbolAddress((void**)&xl, g_xl);
    cudaGetSymbolAddress((void**)&wqh, g_wqh);
    cudaGetSymbolAddress((void**)&wql, g_wql);
    cudaGetSymbolAddress((void**)&wph, g_wph);
    cudaGetSymbolAddress((void**)&wpl, g_wpl);
    cudaGetSymbolAddress((void**)&ah, g_ah);
    cudaGetSymbolAddress((void**)&al, g_al);

    // 0) pre-split inputs
    split_kernel<<<(MR * CC / 4 + 255) / 256, 256>>>(x, xh, xl, MR * CC / 4);
    split_kernel<<<(3 * CC * CC / 4 + 255) / 256, 256>>>(w_qkv, wqh, wql, 3 * CC * CC / 4);
    split_kernel<<<(CC * CC / 4 + 255) / 256, 256>>>(w_proj, wph, wpl, CC * CC / 4);

    // 1) qkv = x @ w_qkv^T
    gemm_b16<<<dim3(3 * CC / 128, MR / 128), 256>>>(xh, xl, wqh, wql, nullptr,
                                                    qkv, MR, 3 * CC, CC);
    // 2) RoPE + split q/k/v (head-contiguous)
    prep_qkv<<<(BB * NN * HH * 2) / 256, 256>>>(qkv, freqs);

    // 3) attention (outputs pre-split g_ah/g_al)
    attn_mma<<<dim3(NN / 128, HH, BB), 256>>>();

    // 4) out = attn @ w_proj^T + b_proj
    gemm_b16<<<dim3(CC / 128, MR / 128), 256>>>(ah, al, wph, wpl, b_proj,
                                                out, MR, CC, CC);
}

// round 7
// speedup vs baseline: 7.0552x; 1.1528x over previous
#include <cuda_runtime.h>
#include <cuda_bf16.h>
#include <math.h>
#include <stdint.h>

#define BB 2
#define NN 2048
#define CC 1024
#define HH 16
#define DD 64
#define MR (BB*NN)          // 4096 rows
#define QK_SCALE 0.125f     // 64^-0.5

// ---- global scratch (allocation-free rule) --------------------------------
__device__ float g_qkv[(size_t)MR * 3 * CC];                  // fp32 qkv
__device__ __nv_bfloat16 g_xh[(size_t)MR * CC],  g_xl[(size_t)MR * CC];
__device__ __nv_bfloat16 g_wqh[(size_t)3 * CC * CC], g_wql[(size_t)3 * CC * CC];
__device__ __nv_bfloat16 g_wph[(size_t)CC * CC], g_wpl[(size_t)CC * CC];
__device__ __nv_bfloat16 g_ah[(size_t)MR * CC],  g_al[(size_t)MR * CC];
// RoPE'd, split, head-contiguous [b][h][n][64]
__device__ __nv_bfloat16 g_Qh[(size_t)MR * CC], g_Ql[(size_t)MR * CC];
__device__ __nv_bfloat16 g_Kh[(size_t)MR * CC], g_Kl[(size_t)MR * CC];
__device__ __nv_bfloat16 g_Vh[(size_t)MR * CC], g_Vl[(size_t)MR * CC];

// ---- helpers --------------------------------------------------------------
__device__ __forceinline__ uint32_t smem_u32(const void* p) {
    return (uint32_t)__cvta_generic_to_shared(p);
}
__device__ __forceinline__ void cp16(uint32_t dst, const void* src) {
    asm volatile("cp.async.ca.shared.global [%0], [%1], 16;"
                 :: "r"(dst), "l"(src) : "memory");
}
__device__ __forceinline__ void cp_commit() {
    asm volatile("cp.async.commit_group;" ::: "memory");
}
__device__ __forceinline__ void cp_wait1() {
    asm volatile("cp.async.wait_group 1;" ::: "memory");
}
__device__ __forceinline__ void ldmx4(uint32_t* r, uint32_t addr) {
    asm volatile("ldmatrix.sync.aligned.m8n8.x4.shared.b16 {%0,%1,%2,%3}, [%4];"
                 : "=r"(r[0]), "=r"(r[1]), "=r"(r[2]), "=r"(r[3]) : "r"(addr));
}
__device__ __forceinline__ void ldmx4t(uint32_t* r, uint32_t addr) {
    asm volatile("ldmatrix.sync.aligned.m8n8.x4.trans.shared.b16 {%0,%1,%2,%3}, [%4];"
                 : "=r"(r[0]), "=r"(r[1]), "=r"(r[2]), "=r"(r[3]) : "r"(addr));
}
__device__ __forceinline__ void mma_bf16(float* c, const uint32_t* a, const uint32_t* b) {
    asm volatile(
        "mma.sync.aligned.m16n8k16.row.col.f32.bf16.bf16.f32 "
        "{%0,%1,%2,%3}, {%4,%5,%6,%7}, {%8,%9}, {%0,%1,%2,%3};"
        : "+f"(c[0]), "+f"(c[1]), "+f"(c[2]), "+f"(c[3])
        : "r"(a[0]), "r"(a[1]), "r"(a[2]), "r"(a[3]), "r"(b[0]), "r"(b[1]));
}
__device__ __forceinline__ uint32_t pack2bf(float x, float y) {
    __nv_bfloat162 h = __floats2bfloat162_rn(x, y);
    return *(uint32_t*)&h;
}
__device__ __forceinline__ void split2(float x, float y, uint32_t& hi, uint32_t& lo) {
    float hx = __bfloat162float(__float2bfloat16(x));
    float hy = __bfloat162float(__float2bfloat16(y));
    hi = pack2bf(hx, hy);
    lo = pack2bf(x - hx, y - hy);
}

// ---------------------------------------------------------------------------
// split fp32 -> hi/lo bf16 (vectorized by 4)
// ---------------------------------------------------------------------------
__global__ void split_kernel(const float* __restrict__ src,
                             __nv_bfloat16* __restrict__ hi,
                             __nv_bfloat16* __restrict__ lo, int n4) {
    int i = blockIdx.x * blockDim.x + threadIdx.x;
    if (i >= n4) return;
    float4 v = ((const float4*)src)[i];
    uint32_t h0, l0, h1, l1;
    split2(v.x, v.y, h0, l0);
    split2(v.z, v.w, h1, l1);
    ((uint2*)hi)[i] = make_uint2(h0, h1);
    ((uint2*)lo)[i] = make_uint2(l0, l1);
}

// ---------------------------------------------------------------------------
// prep: RoPE q/k (+scale q), split q/k/v into [b][h][n][64]
// ---------------------------------------------------------------------------
__global__ void prep_qkv(const float* __restrict__ qkv,
                         const float* __restrict__ freqs) {
    int gid = blockIdx.x * blockDim.x + threadIdx.x;
    int half = gid & 1;
    int h = (gid >> 1) & (HH - 1);
    int n = (gid >> 5) & (NN - 1);
    int b = gid >> 16;

    const float* base = qkv + (size_t)(b * NN + n) * 3 * CC + h * DD + half * 32;
    const float* fp = freqs + (size_t)n * 32 + half * 16;
    size_t orow = ((size_t)(b * HH + h) * NN + n) * 64 + half * 32;

#pragma unroll
    for (int j = 0; j < 32; j += 4) {
        float c0, s0, c1, s1;
        __sincosf(fp[j / 2], &s0, &c0);
        __sincosf(fp[j / 2 + 1], &s1, &c1);
        uint32_t hi0, lo0, hi1, lo1;

        float4 q = *(const float4*)(base + j);
        split2((q.x * c0 - q.y * s0) * QK_SCALE, (q.x * s0 + q.y * c0) * QK_SCALE, hi0, lo0);
        split2((q.z * c1 - q.w * s1) * QK_SCALE, (q.z * s1 + q.w * c1) * QK_SCALE, hi1, lo1);
        *(uint2*)(g_Qh + orow + j) = make_uint2(hi0, hi1);
        *(uint2*)(g_Ql + orow + j) = make_uint2(lo0, lo1);

        float4 k = *(const float4*)(base + CC + j);
        split2(k.x * c0 - k.y * s0, k.x * s0 + k.y * c0, hi0, lo0);
        split2(k.z * c1 - k.w * s1, k.z * s1 + k.w * c1, hi1, lo1);
        *(uint2*)(g_Kh + orow + j) = make_uint2(hi0, hi1);
        *(uint2*)(g_Kl + orow + j) = make_uint2(lo0, lo1);

        float4 v = *(const float4*)(base + 2 * CC + j);
        split2(v.x, v.y, hi0, lo0);
        split2(v.z, v.w, hi1, lo1);
        *(uint2*)(g_Vh + orow + j) = make_uint2(hi0, hi1);
        *(uint2*)(g_Vl + orow + j) = make_uint2(lo0, lo1);
    }
}

// ---------------------------------------------------------------------------
// GEMM, pre-split bf16, cp.async double-buffered. Cm = A @ W^T (+bias).
// CTA 128x128, K-chunk 32, 8 warps (64x32 warp tile), 3-term split MMAs.
// Dynamic smem: 2 stages x (Ah|Al|Bh|Bl)[128][40] bf16 = 81920 B.
// ---------------------------------------------------------------------------
#define SPAD 40
#define G_ARR (128 * SPAD * 2)      // 10240 B per array
#define G_STAGE (4 * G_ARR)         // 40960 B per stage

__global__ __launch_bounds__(256, 2) void gemm_b16(
        const __nv_bfloat16* __restrict__ Ahg, const __nv_bfloat16* __restrict__ Alg,
        const __nv_bfloat16* __restrict__ Whg, const __nv_bfloat16* __restrict__ Wlg,
        const float* __restrict__ bias, float* __restrict__ Cm,
        int M, int Nc, int K) {
    extern __shared__ __align__(16) char sm[];
    const uint32_t sbase = smem_u32(sm);

    const int tid = threadIdx.x;
    const int wid = tid >> 5;
    const int lane = tid & 31;
    const int m0 = blockIdx.y * 128;
    const int n0 = blockIdx.x * 128;
    const int wm = (wid >> 2) * 64;
    const int wn = (wid & 3) * 32;

    const int lrow = tid >> 1;
    const int lcol = (tid & 1) * 16;
    const __nv_bfloat16* Ahp = Ahg + (size_t)(m0 + lrow) * K + lcol;
    const __nv_bfloat16* Alp = Alg + (size_t)(m0 + lrow) * K + lcol;
    const __nv_bfloat16* Whp = Whg + (size_t)(n0 + lrow) * K + lcol;
    const __nv_bfloat16* Wlp = Wlg + (size_t)(n0 + lrow) * K + lcol;
    const uint32_t ldst = sbase + (lrow * SPAD + lcol) * 2;

    float acc[4][4][4];
#pragma unroll
    for (int i = 0; i < 4; i++)
#pragma unroll
        for (int j = 0; j < 4; j++)
#pragma unroll
            for (int f = 0; f < 4; f++) acc[i][j][f] = 0.f;

    const uint32_t a_row = wm + (lane & 15);
    const uint32_t a_coff = (lane >> 4) * 8;
    const uint32_t b_row = wn + ((lane >> 4) << 3) + (lane & 7);
    const uint32_t b_coff = ((lane >> 3) & 1) * 8;

    // prefetch stage 0
    {
        uint32_t d = ldst;
        cp16(d, Ahp); cp16(d + 16, Ahp + 8);
        cp16(d + G_ARR, Alp); cp16(d + G_ARR + 16, Alp + 8);
        cp16(d + 2 * G_ARR, Whp); cp16(d + 2 * G_ARR + 16, Whp + 8);
        cp16(d + 3 * G_ARR, Wlp); cp16(d + 3 * G_ARR + 16, Wlp + 8);
    }
    cp_commit();

    int buf = 0;
    for (int k0 = 0; k0 < K; k0 += 32) {
        if (k0 + 32 < K) {
            uint32_t d = ldst + (buf ^ 1) * G_STAGE;
            int kn = k0 + 32;
            cp16(d, Ahp + kn); cp16(d + 16, Ahp + kn + 8);
            cp16(d + G_ARR, Alp + kn); cp16(d + G_ARR + 16, Alp + kn + 8);
            cp16(d + 2 * G_ARR, Whp + kn); cp16(d + 2 * G_ARR + 16, Whp + kn + 8);
            cp16(d + 3 * G_ARR, Wlp + kn); cp16(d + 3 * G_ARR + 16, Wlp + kn + 8);
        }
        cp_commit();
        cp_wait1();
        __syncthreads();

        const uint32_t sAh = sbase + buf * G_STAGE;
        const uint32_t sAl = sAh + G_ARR;
        const uint32_t sBh = sAh + 2 * G_ARR;
        const uint32_t sBl = sAh + 3 * G_ARR;

#pragma unroll
        for (int ks = 0; ks < 2; ks++) {
            const uint32_t kc = ks * 16;
            uint32_t afh[4][4], afl[4][4];
#pragma unroll
            for (int mt = 0; mt < 4; mt++) {
                uint32_t off = ((a_row + mt * 16) * SPAD + kc + a_coff) * 2;
                ldmx4(afh[mt], sAh + off);
                ldmx4(afl[mt], sAl + off);
            }
            uint32_t bfh[2][4], bfl[2][4];
#pragma unroll
            for (int bt = 0; bt < 2; bt++) {
                uint32_t off = ((b_row + bt * 16) * SPAD + kc + b_coff) * 2;
                ldmx4(bfh[bt], sBh + off);
                ldmx4(bfl[bt], sBl + off);
            }
#pragma unroll
            for (int mt = 0; mt < 4; mt++)
#pragma unroll
                for (int nt = 0; nt < 4; nt++) {
                    uint32_t* bh = &bfh[nt >> 1][(nt & 1) * 2];
                    uint32_t* bl = &bfl[nt >> 1][(nt & 1) * 2];
                    mma_bf16(acc[mt][nt], afh[mt], bh);
                    mma_bf16(acc[mt][nt], afh[mt], bl);
                    mma_bf16(acc[mt][nt], afl[mt], bh);
                }
        }
        __syncthreads();
        buf ^= 1;
    }

    const int erow = lane >> 2;
    const int ecol = (lane & 3) * 2;
#pragma unroll
    for (int mt = 0; mt < 4; mt++) {
#pragma unroll
        for (int nt = 0; nt < 4; nt++) {
            int gr = m0 + wm + mt * 16 + erow;
            int gc = n0 + wn + nt * 8 + ecol;
            float b0 = 0.f, b1 = 0.f;
            if (bias) { b0 = bias[gc]; b1 = bias[gc + 1]; }
            *(float2*)(Cm + (size_t)gr * Nc + gc) =
                make_float2(acc[mt][nt][0] + b0, acc[mt][nt][1] + b1);
            *(float2*)(Cm + (size_t)(gr + 8) * Nc + gc) =
                make_float2(acc[mt][nt][2] + b0, acc[mt][nt][3] + b1);
        }
    }
}

// ---------------------------------------------------------------------------
// Flash attention, pre-split bf16, cp.async double-buffered K/V.
// CTA: 128 q-rows x head x batch, 8 warps.
// Dynamic smem: Q (36864) + 2 KV stages (36864 each) = 110592 B.
// ---------------------------------------------------------------------------
#define APAD 72
#define A_QARR (128 * APAD * 2)       // 18432 B (Qh or Ql)
#define A_KARR (64 * APAD * 2)        // 9216 B per KV array
#define A_KSTAGE (4 * A_KARR)         // 36864 B per stage
#define A_KBASE (2 * A_QARR)          // 36864

__global__ __launch_bounds__(256, 1) void attn_mma(void) {
    extern __shared__ __align__(16) char sm[];
    const uint32_t sbase = smem_u32(sm);

    const int t = threadIdx.x;
    const int wid = t >> 5;
    const int lane = t & 31;
    const int h = blockIdx.y;
    const int b = blockIdx.z;
    const int q0 = blockIdx.x * 128;

    const size_t hbase = (size_t)(b * HH + h) * NN * 64;

    // KV loader mapping
    const int krow = t >> 2, kc16 = (t & 3) * 16;
    const uint32_t kdst = sbase + A_KBASE + (krow * APAD + kc16) * 2;
    const size_t ksrc0 = hbase + (size_t)krow * 64 + kc16;

    // ---- prefetch K/V block 0 before anything else ----
    {
        uint32_t d = kdst;
        cp16(d, g_Kh + ksrc0); cp16(d + 16, g_Kh + ksrc0 + 8);
        cp16(d + A_KARR, g_Kl + ksrc0); cp16(d + A_KARR + 16, g_Kl + ksrc0 + 8);
        cp16(d + 2 * A_KARR, g_Vh + ksrc0); cp16(d + 2 * A_KARR + 16, g_Vh + ksrc0 + 8);
        cp16(d + 3 * A_KARR, g_Vl + ksrc0); cp16(d + 3 * A_KARR + 16, g_Vl + ksrc0 + 8);
    }
    cp_commit();

    // ---- stage Q ----
    __nv_bfloat16* const Qh = (__nv_bfloat16*)sm;
    __nv_bfloat16* const Ql = Qh + 128 * APAD;
    {
        int row = t >> 1, half = (t & 1) * 32;
        size_t src = hbase + (size_t)(q0 + row) * 64 + half;
        size_t dst = (size_t)row * APAD + half;
#pragma unroll
        for (int j = 0; j < 32; j += 8) {
            *(uint4*)(Qh + dst + j) = *(const uint4*)(g_Qh + src + j);
            *(uint4*)(Ql + dst + j) = *(const uint4*)(g_Ql + src + j);
        }
    }
    __syncthreads();

    // ---- Q fragments to registers ----
    uint32_t qfh[4][4], qfl[4][4];
    {
        const uint32_t arow = wid * 16 + (lane & 15);
        const uint32_t acoff = (lane >> 4) * 8;
#pragma unroll
        for (int ks = 0; ks < 4; ks++) {
            uint32_t off = (arow * APAD + ks * 16 + acoff) * 2;
            ldmx4(qfh[ks], sbase + off);
            ldmx4(qfl[ks], sbase + A_QARR + off);
        }
    }

    float o[8][4];
#pragma unroll
    for (int i = 0; i < 8; i++)
#pragma unroll
        for (int f = 0; f < 4; f++) o[i][f] = 0.f;
    float m0 = -1e30f, m1 = -1e30f, l0 = 0.f, l1 = 0.f;

    const uint32_t b_row = ((lane >> 4) << 3) + (lane & 7);
    const uint32_t b_coff = ((lane >> 3) & 1) * 8;
    const uint32_t v_row = ((lane >> 3) & 1) * 8 + (lane & 7);
    const uint32_t v_coff = (lane >> 4) * 8;

    int buf = 0;
    for (int kt = 0; kt < NN / 64; kt++) {
        if (kt + 1 < NN / 64) {
            uint32_t d = kdst + (buf ^ 1) * A_KSTAGE;
            size_t src = ksrc0 + (size_t)(kt + 1) * 64 * 64;
            cp16(d, g_Kh + src); cp16(d + 16, g_Kh + src + 8);
            cp16(d + A_KARR, g_Kl + src); cp16(d + A_KARR + 16, g_Kl + src + 8);
            cp16(d + 2 * A_KARR, g_Vh + src); cp16(d + 2 * A_KARR + 16, g_Vh + src + 8);
            cp16(d + 3 * A_KARR, g_Vl + src); cp16(d + 3 * A_KARR + 16, g_Vl + src + 8);
        }
        cp_commit();
        cp_wait1();
        __syncthreads();

        const uint32_t sKh = sbase + A_KBASE + buf * A_KSTAGE;
        const uint32_t sKl = sKh + A_KARR;
        const uint32_t sVh = sKh + 2 * A_KARR;
        const uint32_t sVl = sKh + 3 * A_KARR;

        // ---- S = Q.K^T ----
        float s[8][4];
#pragma unroll
        for (int i = 0; i < 8; i++)
#pragma unroll
            for (int f = 0; f < 4; f++) s[i][f] = 0.f;
#pragma unroll
        for (int ks = 0; ks < 4; ks++) {
            const uint32_t kc = ks * 16;
#pragma unroll
            for (int g = 0; g < 4; g++) {
                uint32_t bh[4], bl[4];
                uint32_t off = ((g * 16 + b_row) * APAD + kc + b_coff) * 2;
                ldmx4(bh, sKh + off);
                ldmx4(bl, sKl + off);
                mma_bf16(s[2 * g],     qfh[ks], &bh[0]);
                mma_bf16(s[2 * g],     qfh[ks], &bl[0]);
                mma_bf16(s[2 * g],     qfl[ks], &bh[0]);
                mma_bf16(s[2 * g + 1], qfh[ks], &bh[2]);
                mma_bf16(s[2 * g + 1], qfh[ks], &bl[2]);
                mma_bf16(s[2 * g + 1], qfl[ks], &bh[2]);
            }
        }

        // ---- online softmax ----
        float tm0 = -1e30f, tm1 = -1e30f;
#pragma unroll
        for (int nt = 0; nt < 8; nt++) {
            tm0 = fmaxf(tm0, fmaxf(s[nt][0], s[nt][1]));
            tm1 = fmaxf(tm1, fmaxf(s[nt][2], s[nt][3]));
        }
        tm0 = fmaxf(tm0, __shfl_xor_sync(0xffffffffu, tm0, 1));
        tm0 = fmaxf(tm0, __shfl_xor_sync(0xffffffffu, tm0, 2));
        tm1 = fmaxf(tm1, __shfl_xor_sync(0xffffffffu, tm1, 1));
        tm1 = fmaxf(tm1, __shfl_xor_sync(0xffffffffu, tm1, 2));
        float mn0 = fmaxf(m0, tm0), mn1 = fmaxf(m1, tm1);
        float al0 = __expf(m0 - mn0), al1 = __expf(m1 - mn1);
        m0 = mn0; m1 = mn1;
        float rs0 = 0.f, rs1 = 0.f;
#pragma unroll
        for (int nt = 0; nt < 8; nt++) {
            s[nt][0] = __expf(s[nt][0] - m0);
            s[nt][1] = __expf(s[nt][1] - m0);
            s[nt][2] = __expf(s[nt][2] - m1);
            s[nt][3] = __expf(s[nt][3] - m1);
            rs0 += s[nt][0] + s[nt][1];
            rs1 += s[nt][2] + s[nt][3];
        }
        rs0 += __shfl_xor_sync(0xffffffffu, rs0, 1);
        rs0 += __shfl_xor_sync(0xffffffffu, rs0, 2);
        rs1 += __shfl_xor_sync(0xffffffffu, rs1, 1);
        rs1 += __shfl_xor_sync(0xffffffffu, rs1, 2);
        l0 = l0 * al0 + rs0;
        l1 = l1 * al1 + rs1;
#pragma unroll
        for (int nt = 0; nt < 8; nt++) {
            o[nt][0] *= al0; o[nt][1] *= al0;
            o[nt][2] *= al1; o[nt][3] *= al1;
        }

        // ---- pack P hi/lo ----
        uint32_t ph[4][4], pl[4][4];
#pragma unroll
        for (int ks = 0; ks < 4; ks++) {
#pragma unroll
            for (int hf = 0; hf < 2; hf++) {
                int nt = 2 * ks + hf;
                split2(s[nt][0], s[nt][1], ph[ks][hf * 2 + 0], pl[ks][hf * 2 + 0]);
                split2(s[nt][2], s[nt][3], ph[ks][hf * 2 + 1], pl[ks][hf * 2 + 1]);
            }
        }

        // ---- O += P.V ----
#pragma unroll
        for (int ks = 0; ks < 4; ks++) {
            const uint32_t kr = ks * 16 + v_row;
#pragma unroll
            for (int g = 0; g < 4; g++) {
                uint32_t vh4[4], vl4[4];
                uint32_t off = (kr * APAD + g * 16 + v_coff) * 2;
                ldmx4t(vh4, sVh + off);
                ldmx4t(vl4, sVl + off);
                mma_bf16(o[2 * g],     ph[ks], &vh4[0]);
                mma_bf16(o[2 * g],     ph[ks], &vl4[0]);
                mma_bf16(o[2 * g],     pl[ks], &vh4[0]);
                mma_bf16(o[2 * g + 1], ph[ks], &vh4[2]);
                mma_bf16(o[2 * g + 1], ph[ks], &vl4[2]);
                mma_bf16(o[2 * g + 1], pl[ks], &vh4[2]);
            }
        }
        __syncthreads();
        buf ^= 1;
    }

    // ---- epilogue: write output pre-split ----
    float inv0 = 1.f / l0, inv1 = 1.f / l1;
    int r0 = q0 + wid * 16 + (lane >> 2);
    int cbase = (lane & 3) * 2;
    size_t base0 = (size_t)(b * NN + r0) * CC + h * DD + cbase;
    size_t base1 = base0 + (size_t)8 * CC;
#pragma unroll
    for (int nt = 0; nt < 8; nt++) {
        uint32_t hi, lo;
        split2(o[nt][0] * inv0, o[nt][1] * inv0, hi, lo);
        *(uint32_t*)(g_ah + base0 + nt * 8) = hi;
        *(uint32_t*)(g_al + base0 + nt * 8) = lo;
        split2(o[nt][2] * inv1, o[nt][3] * inv1, hi, lo);
        *(uint32_t*)(g_ah + base1 + nt * 8) = hi;
        *(uint32_t*)(g_al + base1 + nt * 8) = lo;
    }
}

// ---------------------------------------------------------------------------
extern "C" void kernel_launch(void* const* d_in, const int* in_sizes, int n_in,
                              void* d_out, int out_size) {
    const float* x      = (const float*)d_in[0];
    const float* freqs  = (const float*)d_in[1];
    const float* w_qkv  = (const float*)d_in[2];
    const float* w_proj = (const float*)d_in[3];
    const float* b_proj = (const float*)d_in[4];
    float* out = (float*)d_out;

    float* qkv;
    cudaGetSymbolAddress((void**)&qkv, g_qkv);
    __nv_bfloat16 *xh, *xl, *wqh, *wql, *wph, *wpl, *ah, *al;
    cudaGetSymbolAddress((void**)&xh, g_xh);
    cudaGetSymbolAddress((void**)&xl, g_xl);
    cudaGetSymbolAddress((void**)&wqh, g_wqh);
    cudaGetSymbolAddress((void**)&wql, g_wql);
    cudaGetSymbolAddress((void**)&wph, g_wph);
    cudaGetSymbolAddress((void**)&wpl, g_wpl);
    cudaGetSymbolAddress((void**)&ah, g_ah);
    cudaGetSymbolAddress((void**)&al, g_al);

    static int smem_set = 0;
    if (!smem_set) {
        cudaFuncSetAttribute(gemm_b16, cudaFuncAttributeMaxDynamicSharedMemorySize,
                             2 * G_STAGE);
        cudaFuncSetAttribute(attn_mma, cudaFuncAttributeMaxDynamicSharedMemorySize,
                             A_KBASE + 2 * A_KSTAGE);
        smem_set = 1;
    }

    // 0) pre-split inputs
    split_kernel<<<(MR * CC / 4 + 255) / 256, 256>>>(x, xh, xl, MR * CC / 4);
    split_kernel<<<(3 * CC * CC / 4 + 255) / 256, 256>>>(w_qkv, wqh, wql, 3 * CC * CC / 4);
    split_kernel<<<(CC * CC / 4 + 255) / 256, 256>>>(w_proj, wph, wpl, CC * CC / 4);

    // 1) qkv = x @ w_qkv^T
    gemm_b16<<<dim3(3 * CC / 128, MR / 128), 256, 2 * G_STAGE>>>(
        xh, xl, wqh, wql, nullptr, qkv, MR, 3 * CC, CC);
    // 2) RoPE + split q/k/v (head-contiguous)
    prep_qkv<<<(BB * NN * HH * 2) / 256, 256>>>(qkv, freqs);
    // 3) attention (outputs pre-split g_ah/g_al)
    attn_mma<<<dim3(NN / 128, HH, BB), 256, A_KBASE + 2 * A_KSTAGE>>>();
    // 4) out = attn @ w_proj^T + b_proj
    gemm_b16<<<dim3(CC / 128, MR / 128), 256, 2 * G_STAGE>>>(
        ah, al, wph, wpl, b_proj, out, MR, CC, CC);
}